// round 3
// baseline (speedup 1.0000x reference)
#include <cuda_runtime.h>
#include <math.h>

#define N_NODES 20000
#define RP 8
#define EMB 64
#define NCLS 16
#define NT 250000
#define NRP (N_NODES * RP)
#define NRELS 64

// ---------------- scratch (static device globals; no allocation) ----------------
__device__ __align__(16) float g_l1[(size_t)NT * RP];          //  8 MB  l1[t][r]
__device__ __align__(16) float g_l2[(size_t)NT * RP];          //  8 MB  l2[t][r]
__device__ __align__(16) float g_colsum[NRP];                  // 640 KB
__device__ __align__(16) float g_rowsum[NRP];                  // 640 KB
__device__ __align__(16) float g_h[(size_t)N_NODES * EMB];     //  5 MB
__device__ __align__(16) float g_h2[(size_t)NRP * EMB];        // 41 MB

// ---------------- kernel 0: zero the accumulators ----------------
__global__ void k_zero() {
    size_t tid = (size_t)blockIdx.x * blockDim.x + threadIdx.x;
    size_t stride = (size_t)gridDim.x * blockDim.x;
    float4 z = make_float4(0.f, 0.f, 0.f, 0.f);
    for (size_t i = tid; i < NRP / 4; i += stride) {
        ((float4*)g_colsum)[i] = z;
        ((float4*)g_rowsum)[i] = z;
    }
    for (size_t i = tid; i < ((size_t)N_NODES * EMB) / 4; i += stride)
        ((float4*)g_h)[i] = z;
    for (size_t i = tid; i < ((size_t)NRP * EMB) / 4; i += stride)
        ((float4*)g_h2)[i] = z;
}

// ---------------- kernel 1: l1, l2(softmax), colsum, rowsum ----------------
// One warp per triple. Lane k loads relation_matrix[t][k] AND [t][k+32] (full
// 64-wide row); butterfly-reduce 8 accumulators for each of the two 64x8
// matvecs; lanes 0..7 finish per-r work. r==0 contributions (colsum[0],
// rowsum[0]) are block-reduced to kill the 250k-to-one-address atomic storm.
__global__ void k_phaseA(const float* __restrict__ rm,
                         const int* __restrict__ hrow,
                         const int* __restrict__ vcol,
                         const float* __restrict__ Wl1, const float* __restrict__ bl1,
                         const float* __restrict__ Wl2, const float* __restrict__ bl2) {
    __shared__ float sW1[NRELS * RP];
    __shared__ float sW2[NRELS * RP];
    __shared__ float sb1[RP], sb2[RP];
    __shared__ float s_cs0, s_rs0;

    int tid = threadIdx.x;
    for (int i = tid; i < NRELS * RP; i += blockDim.x) { sW1[i] = Wl1[i]; sW2[i] = Wl2[i]; }
    if (tid < RP) { sb1[tid] = bl1[tid]; sb2[tid] = bl2[tid]; }
    if (tid == 0) { s_cs0 = 0.f; s_rs0 = 0.f; }
    __syncthreads();

    int lane = tid & 31;
    int warpInBlk = tid >> 5;
    int warpId = blockIdx.x * (blockDim.x >> 5) + warpInBlk;
    int nwarps = gridDim.x * (blockDim.x >> 5);

    float cs0_acc = 0.f, rs0_acc = 0.f;

    for (int t = warpId; t < NT; t += nwarps) {
        // full 64-entry relation row: lane covers k = lane and k = lane+32
        float x0 = rm[(size_t)t * 64 + lane];
        float x1 = rm[(size_t)t * 64 + 32 + lane];
        float a1[8], a2[8];
#pragma unroll
        for (int r = 0; r < 8; r++) {
            a1[r] = x0 * sW1[lane * 8 + r] + x1 * sW1[(lane + 32) * 8 + r];
            a2[r] = x0 * sW2[lane * 8 + r] + x1 * sW2[(lane + 32) * 8 + r];
        }
#pragma unroll
        for (int off = 16; off > 0; off >>= 1) {
#pragma unroll
            for (int r = 0; r < 8; r++) {
                a1[r] += __shfl_xor_sync(0xffffffffu, a1[r], off);
                a2[r] += __shfl_xor_sync(0xffffffffu, a2[r], off);
            }
        }
        // every lane now holds the full 8 sums of each matvec
        int s = hrow[t];
        int o = vcol[t];
        if (lane < 8) {
            int r = lane;
            float l1v = a1[r] + sb1[r];
            g_l1[(size_t)t * 8 + r] = l1v;

            // softmax over the 8 l2 logits (each lane has all 8 locally)
            float m = -1e30f;
            float z[8];
#pragma unroll
            for (int q = 0; q < 8; q++) { z[q] = a2[q] + sb2[q]; m = fmaxf(m, z[q]); }
            float ssum = 0.f;
#pragma unroll
            for (int q = 0; q < 8; q++) ssum += expf(z[q] - m);
            float l2v = expf(z[r] - m) / ssum;   // relu is a no-op (softmax > 0)
            g_l2[(size_t)t * 8 + r] = l2v;

            if (r == 0) {
                cs0_acc += l1v;     // hcol = o*0 = 0
                rs0_acc += l2v;     // vrow = s*0 = 0
            } else {
                atomicAdd(&g_colsum[o * r], l1v);
                atomicAdd(&g_rowsum[s * r], l2v);
            }
        }
    }
    if (lane == 0) { atomicAdd(&s_cs0, cs0_acc); atomicAdd(&s_rs0, rs0_acc); }
    __syncthreads();
    if (tid == 0) {
        atomicAdd(&g_colsum[0], s_cs0);
        atomicAdd(&g_rowsum[0], s_rs0);
    }
}

// ---------------- kernel 2: h[s] += sum_r (l1[t][r]/colsum[o*r]) * W1flat[o*r] ----------------
// One warp per triple; each lane owns 2 of the 64 embedding floats.
__global__ void k_hscatter(const int* __restrict__ hrow,
                           const int* __restrict__ vcol,
                           const float* __restrict__ W1) {
    int tid = threadIdx.x;
    int lane = tid & 31;
    int warpId = blockIdx.x * (blockDim.x >> 5) + (tid >> 5);
    int nwarps = gridDim.x * (blockDim.x >> 5);

    // r=0 always gathers flat row 0 — load it once
    const float2 w0v = *(const float2*)&W1[lane * 2];

    for (int t = warpId; t < NT; t += nwarps) {
        int s = hrow[t];
        int o = vcol[t];
        float cr = 0.f;
        if (lane < 8)
            cr = g_l1[(size_t)t * 8 + lane] / g_colsum[o * lane];

        float w0 = __shfl_sync(0xffffffffu, cr, 0);
        float accx = w0 * w0v.x;
        float accy = w0 * w0v.y;
#pragma unroll
        for (int r = 1; r < 8; r++) {
            float w = __shfl_sync(0xffffffffu, cr, r);
            const float2 wv = *(const float2*)&W1[(size_t)(o * r) * 64 + lane * 2];
            accx += w * wv.x;
            accy += w * wv.y;
        }
        atomicAdd((float2*)&g_h[(size_t)s * 64 + lane * 2], make_float2(accx, accy));
    }
}

// ---------------- kernel 2.5: h = relu(h + bias1) ----------------
__global__ void k_biasrelu(const float* __restrict__ bias1) {
    int tid = blockIdx.x * blockDim.x + threadIdx.x;
    int stride = gridDim.x * blockDim.x;
    for (int i = tid; i < N_NODES * EMB; i += stride)
        g_h[i] = fmaxf(g_h[i] + bias1[i & 63], 0.f);
}

// ---------------- kernel 3: h2[s*r] += (l2[t][r]/max(rowsum[s*r],1e-6)) * h[o] ----------------
// One warp per triple, lane owns 2 floats. r==0 (segment 0 for ALL triples) is
// accumulated in registers -> shared -> one global float atomic per block-lane.
__global__ void k_h2scatter(const int* __restrict__ hrow,
                            const int* __restrict__ vcol) {
    __shared__ float sh0[EMB];
    int tid = threadIdx.x;
    if (tid < EMB) sh0[tid] = 0.f;
    __syncthreads();

    int lane = tid & 31;
    int warpId = blockIdx.x * (blockDim.x >> 5) + (tid >> 5);
    int nwarps = gridDim.x * (blockDim.x >> 5);

    float rs0 = fmaxf(g_rowsum[0], 1e-6f);
    float z0x = 0.f, z0y = 0.f;

    for (int t = warpId; t < NT; t += nwarps) {
        int s = hrow[t];
        int o = vcol[t];
        float2 hv = *(const float2*)&g_h[(size_t)o * 64 + lane * 2];

        float lr = 0.f;
        if (lane < 8) {
            float denom = (lane == 0) ? rs0 : fmaxf(g_rowsum[s * lane], 1e-6f);
            lr = g_l2[(size_t)t * 8 + lane] / denom;
        }

        float w0 = __shfl_sync(0xffffffffu, lr, 0);
        z0x += w0 * hv.x;
        z0y += w0 * hv.y;
#pragma unroll
        for (int r = 1; r < 8; r++) {
            float w = __shfl_sync(0xffffffffu, lr, r);
            atomicAdd((float2*)&g_h2[(size_t)(s * r) * 64 + lane * 2],
                      make_float2(w * hv.x, w * hv.y));
        }
    }
    atomicAdd(&sh0[lane * 2], z0x);
    atomicAdd(&sh0[lane * 2 + 1], z0y);
    __syncthreads();
    if (tid < EMB) atomicAdd(&g_h2[tid], sh0[tid]);
}

// ---------------- kernel 4: logits[n][c] = bias2[c] + sum_q sum_h W2[q][h][c]*h2[q*N+n][h] ----------------
// One warp per node; lane covers 16 of the 512 (q,h) pairs; W2 transposed in
// shared so lane reads are conflict-free.
__global__ void k_logits(const float* __restrict__ W2,
                         const float* __restrict__ b2,
                         float* __restrict__ out) {
    __shared__ float sW2t[NCLS * RP * EMB];   // [c][q*64+h], 32 KB
    int tid = threadIdx.x;
    for (int i = tid; i < RP * EMB * NCLS; i += blockDim.x) {
        int qh = i >> 4;
        int c = i & 15;
        sW2t[c * (RP * EMB) + qh] = W2[i];
    }
    __syncthreads();

    int lane = tid & 31;
    int warpId = blockIdx.x * (blockDim.x >> 5) + (tid >> 5);
    int nwarps = gridDim.x * (blockDim.x >> 5);

    for (int m = warpId; m < N_NODES; m += nwarps) {
        float acc[NCLS];
#pragma unroll
        for (int c = 0; c < NCLS; c++) acc[c] = 0.f;

#pragma unroll
        for (int i = 0; i < 16; i++) {
            int f = lane + 32 * i;          // f = q*64 + h, f < 512
            int q = f >> 6;
            int h = f & 63;
            float hval = g_h2[((size_t)q * N_NODES + m) * 64 + h];
#pragma unroll
            for (int c = 0; c < NCLS; c++)
                acc[c] += hval * sW2t[c * (RP * EMB) + f];
        }
#pragma unroll
        for (int off = 16; off > 0; off >>= 1) {
#pragma unroll
            for (int c = 0; c < NCLS; c++)
                acc[c] += __shfl_xor_sync(0xffffffffu, acc[c], off);
        }
        if (lane < NCLS)
            out[(size_t)m * NCLS + lane] = acc[lane] + b2[lane];
    }
}

// ---------------- launch ----------------
extern "C" void kernel_launch(void* const* d_in, const int* in_sizes, int n_in,
                              void* d_out, int out_size) {
    const float* rm    = (const float*)d_in[0];   // relation_matrix (NT, 64)
    const int*   hrow  = (const int*)d_in[1];     // s tiled
    // d_in[2] = hcol (derivable: o*r), d_in[3] = vrow (derivable: s*r) — unused
    const int*   vcol  = (const int*)d_in[4];     // o tiled
    const float* Wl1   = (const float*)d_in[5];
    const float* bl1   = (const float*)d_in[6];
    const float* Wl2   = (const float*)d_in[7];
    const float* bl2   = (const float*)d_in[8];
    const float* w1    = (const float*)d_in[9];   // weights1 (8, 20000, 64)
    const float* w2    = (const float*)d_in[10];  // weights2 (8, 64, 16)
    const float* bias1 = (const float*)d_in[11];
    const float* bias2 = (const float*)d_in[12];
    float* out = (float*)d_out;

    k_zero<<<2048, 256>>>();
    k_phaseA<<<2048, 256>>>(rm, hrow, vcol, Wl1, bl1, Wl2, bl2);
    k_hscatter<<<2048, 256>>>(hrow, vcol, w1);
    k_biasrelu<<<1024, 256>>>(bias1);
    k_h2scatter<<<2048, 256>>>(hrow, vcol);
    k_logits<<<2048, 256>>>(w2, bias2, out);
}

// round 4
// speedup vs baseline: 1.0519x; 1.0519x over previous
#include <cuda_runtime.h>
#include <math.h>

#define N_NODES 20000
#define RP 8
#define EMB 64
#define NCLS 16
#define NT 250000
#define NRP (N_NODES * RP)
#define NRELS 64

// ---------------- scratch (static device globals; no allocation) ----------------
__device__ __align__(16) float g_l1[(size_t)NT * RP];          //  8 MB  l1[t][r]
__device__ __align__(16) float g_l2[(size_t)NT * RP];          //  8 MB  l2[t][r]
__device__ __align__(16) float g_colsum[NRP];                  // 640 KB
__device__ __align__(16) float g_rowsum[NRP];                  // 640 KB
__device__ __align__(16) float g_h[(size_t)N_NODES * EMB];     //  5 MB
__device__ __align__(16) float g_h2[(size_t)NRP * EMB];        // 41 MB
__device__ __align__(16) int   g_cnt[N_NODES];                 // per-s triple count
__device__ __align__(16) int   g_cur[N_NODES];                 // fill cursor
__device__ __align__(16) int   g_offs[N_NODES + 1];            // CSR offsets
__device__ __align__(16) int   g_csr[NT];                      // triple ids grouped by s

// ---------------- kernel 0: zero the accumulators ----------------
__global__ void k_zero() {
    size_t tid = (size_t)blockIdx.x * blockDim.x + threadIdx.x;
    size_t stride = (size_t)gridDim.x * blockDim.x;
    float4 z = make_float4(0.f, 0.f, 0.f, 0.f);
    int4 zi = make_int4(0, 0, 0, 0);
    for (size_t i = tid; i < NRP / 4; i += stride) {
        ((float4*)g_colsum)[i] = z;
        ((float4*)g_rowsum)[i] = z;
    }
    for (size_t i = tid; i < N_NODES / 4; i += stride) {
        ((int4*)g_cnt)[i] = zi;
        ((int4*)g_cur)[i] = zi;
    }
    for (size_t i = tid; i < ((size_t)NRP * EMB) / 4; i += stride)
        ((float4*)g_h2)[i] = z;
}

// ---------------- kernel 1: l1, l2(softmax), colsum, rowsum, per-s counts ----------------
// One warp per triple; lane k covers relation entries k and k+32 (full 64-wide
// row). r==0 contributions (colsum[0], rowsum[0]) block-reduced to avoid the
// 250k-to-one atomic storm.
__global__ void k_phaseA(const float* __restrict__ rm,
                         const int* __restrict__ hrow,
                         const int* __restrict__ vcol,
                         const float* __restrict__ Wl1, const float* __restrict__ bl1,
                         const float* __restrict__ Wl2, const float* __restrict__ bl2) {
    __shared__ float sW1[NRELS * RP];
    __shared__ float sW2[NRELS * RP];
    __shared__ float sb1[RP], sb2[RP];
    __shared__ float s_cs0, s_rs0;

    int tid = threadIdx.x;
    for (int i = tid; i < NRELS * RP; i += blockDim.x) { sW1[i] = Wl1[i]; sW2[i] = Wl2[i]; }
    if (tid < RP) { sb1[tid] = bl1[tid]; sb2[tid] = bl2[tid]; }
    if (tid == 0) { s_cs0 = 0.f; s_rs0 = 0.f; }
    __syncthreads();

    int lane = tid & 31;
    int warpId = blockIdx.x * (blockDim.x >> 5) + (tid >> 5);
    int nwarps = gridDim.x * (blockDim.x >> 5);

    float cs0_acc = 0.f, rs0_acc = 0.f;

    for (int t = warpId; t < NT; t += nwarps) {
        float x0 = rm[(size_t)t * 64 + lane];
        float x1 = rm[(size_t)t * 64 + 32 + lane];
        float a1[8], a2[8];
#pragma unroll
        for (int r = 0; r < 8; r++) {
            a1[r] = x0 * sW1[lane * 8 + r] + x1 * sW1[(lane + 32) * 8 + r];
            a2[r] = x0 * sW2[lane * 8 + r] + x1 * sW2[(lane + 32) * 8 + r];
        }
#pragma unroll
        for (int off = 16; off > 0; off >>= 1) {
#pragma unroll
            for (int r = 0; r < 8; r++) {
                a1[r] += __shfl_xor_sync(0xffffffffu, a1[r], off);
                a2[r] += __shfl_xor_sync(0xffffffffu, a2[r], off);
            }
        }
        int s = hrow[t];
        int o = vcol[t];
        if (lane == 8) atomicAdd(&g_cnt[s], 1);   // CSR histogram
        if (lane < 8) {
            int r = lane;
            float l1v = a1[r] + sb1[r];
            g_l1[(size_t)t * 8 + r] = l1v;

            float m = -1e30f;
            float z[8];
#pragma unroll
            for (int q = 0; q < 8; q++) { z[q] = a2[q] + sb2[q]; m = fmaxf(m, z[q]); }
            float ssum = 0.f;
#pragma unroll
            for (int q = 0; q < 8; q++) ssum += expf(z[q] - m);
            float l2v = expf(z[r] - m) / ssum;   // relu no-op (softmax > 0)
            g_l2[(size_t)t * 8 + r] = l2v;

            if (r == 0) {
                cs0_acc += l1v;     // hcol = o*0 = 0
                rs0_acc += l2v;     // vrow = s*0 = 0
            } else {
                atomicAdd(&g_colsum[o * r], l1v);
                atomicAdd(&g_rowsum[s * r], l2v);
            }
        }
    }
    if (lane == 0) { atomicAdd(&s_cs0, cs0_acc); atomicAdd(&s_rs0, rs0_acc); }
    __syncthreads();
    if (tid == 0) {
        atomicAdd(&g_colsum[0], s_cs0);
        atomicAdd(&g_rowsum[0], s_rs0);
    }
}

// ---------------- kernel 1.5: exclusive scan of g_cnt -> g_offs (single block) ----------------
__global__ void k_scan() {
    __shared__ int part[512];
    const int CH = (N_NODES + 511) / 512;   // 40
    int tid = threadIdx.x;
    int base = tid * CH;
    int sum = 0;
    for (int i = 0; i < CH; i++) {
        int idx = base + i;
        if (idx < N_NODES) sum += g_cnt[idx];
    }
    part[tid] = sum;
    __syncthreads();
    for (int off = 1; off < 512; off <<= 1) {
        int v = (tid >= off) ? part[tid - off] : 0;
        __syncthreads();
        part[tid] += v;
        __syncthreads();
    }
    int run = (tid == 0) ? 0 : part[tid - 1];
    for (int i = 0; i < CH; i++) {
        int idx = base + i;
        if (idx < N_NODES) { g_offs[idx] = run; run += g_cnt[idx]; }
    }
    if (tid == 0) g_offs[N_NODES] = NT;
}

// ---------------- kernel 1.6: fill CSR ----------------
__global__ void k_fill(const int* __restrict__ hrow) {
    int t = blockIdx.x * blockDim.x + threadIdx.x;
    if (t < NT) {
        int s = hrow[t];
        int pos = g_offs[s] + atomicAdd(&g_cur[s], 1);
        g_csr[pos] = t;
    }
}

// ---------------- kernel 2: h[s] = relu(bias1 + sum over s's triples) ----------------
// One warp per node s; zero atomics; bias+relu fused.
__global__ void k_h(const int* __restrict__ vcol,
                    const float* __restrict__ W1,
                    const float* __restrict__ bias1) {
    int tid = threadIdx.x;
    int lane = tid & 31;
    int warpId = blockIdx.x * (blockDim.x >> 5) + (tid >> 5);
    int nwarps = gridDim.x * (blockDim.x >> 5);

    const float2 w0v = *(const float2*)&W1[lane * 2];     // flat row 0 (r=0)
    const float2 bv  = *(const float2*)&bias1[lane * 2];
    const float cs0 = g_colsum[0];

    for (int s = warpId; s < N_NODES; s += nwarps) {
        int beg = g_offs[s], end = g_offs[s + 1];
        float accx = 0.f, accy = 0.f, w0sum = 0.f;
        for (int j = beg; j < end; j++) {
            int t = g_csr[j];
            int o = vcol[t];
            float w = 0.f;
            if (lane < 8) {
                float denom = (lane == 0) ? cs0 : g_colsum[o * lane];
                w = g_l1[(size_t)t * 8 + lane] / denom;
            }
            w0sum += __shfl_sync(0xffffffffu, w, 0);
#pragma unroll
            for (int r = 1; r < 8; r++) {
                float wr = __shfl_sync(0xffffffffu, w, r);
                const float2 wv = *(const float2*)&W1[(size_t)(o * r) * 64 + lane * 2];
                accx += wr * wv.x;
                accy += wr * wv.y;
            }
        }
        accx += w0sum * w0v.x;
        accy += w0sum * w0v.y;
        float2 outv = make_float2(fmaxf(accx + bv.x, 0.f), fmaxf(accy + bv.y, 0.f));
        *(float2*)&g_h[(size_t)s * 64 + lane * 2] = outv;
    }
}

// ---------------- kernel 3: h2 scatter, aggregated per node ----------------
// One warp per node s; accumulate all 8 r-slices over the node's triples in
// registers, then 7 float2 atomics per lane per NODE (not per triple).
// r=0 (segment 0 for all triples) goes registers -> shared -> per-block atomic.
__global__ void k_h2(const int* __restrict__ vcol) {
    __shared__ float sh0[EMB];
    int tid = threadIdx.x;
    if (tid < EMB) sh0[tid] = 0.f;
    __syncthreads();

    int lane = tid & 31;
    int warpId = blockIdx.x * (blockDim.x >> 5) + (tid >> 5);
    int nwarps = gridDim.x * (blockDim.x >> 5);

    float a0x = 0.f, a0y = 0.f;    // r=0 accumulator, persists across nodes

    for (int s = warpId; s < N_NODES; s += nwarps) {
        int beg = g_offs[s], end = g_offs[s + 1];
        // per-node reciprocal of rowsum[s*r] (lane r holds r's value; s*0=0 OK)
        float rinv = 0.f;
        if (lane < 8) rinv = 1.f / fmaxf(g_rowsum[s * lane], 1e-6f);

        float ax[8], ay[8];
#pragma unroll
        for (int r = 0; r < 8; r++) { ax[r] = 0.f; ay[r] = 0.f; }

        for (int j = beg; j < end; j++) {
            int t = g_csr[j];
            int o = vcol[t];
            float2 hv = *(const float2*)&g_h[(size_t)o * 64 + lane * 2];
            float lr = 0.f;
            if (lane < 8) lr = g_l2[(size_t)t * 8 + lane] * rinv;
#pragma unroll
            for (int r = 0; r < 8; r++) {
                float w = __shfl_sync(0xffffffffu, lr, r);
                ax[r] += w * hv.x;
                ay[r] += w * hv.y;
            }
        }
        a0x += ax[0];
        a0y += ay[0];
#pragma unroll
        for (int r = 1; r < 8; r++) {
            if (ax[r] != 0.f || ay[r] != 0.f || true) {
                atomicAdd((float2*)&g_h2[(size_t)(s * r) * 64 + lane * 2],
                          make_float2(ax[r], ay[r]));
            }
        }
    }
    atomicAdd(&sh0[lane * 2], a0x);
    atomicAdd(&sh0[lane * 2 + 1], a0y);
    __syncthreads();
    if (tid < EMB) atomicAdd(&g_h2[tid], sh0[tid]);
}

// ---------------- kernel 4: logits ----------------
__global__ void k_logits(const float* __restrict__ W2,
                         const float* __restrict__ b2,
                         float* __restrict__ out) {
    __shared__ float sW2t[NCLS * RP * EMB];   // [c][q*64+h], 32 KB
    int tid = threadIdx.x;
    for (int i = tid; i < RP * EMB * NCLS; i += blockDim.x) {
        int qh = i >> 4;
        int c = i & 15;
        sW2t[c * (RP * EMB) + qh] = W2[i];
    }
    __syncthreads();

    int lane = tid & 31;
    int warpId = blockIdx.x * (blockDim.x >> 5) + (tid >> 5);
    int nwarps = gridDim.x * (blockDim.x >> 5);

    for (int m = warpId; m < N_NODES; m += nwarps) {
        float acc[NCLS];
#pragma unroll
        for (int c = 0; c < NCLS; c++) acc[c] = 0.f;

#pragma unroll
        for (int i = 0; i < 16; i++) {
            int f = lane + 32 * i;          // f = q*64 + h, f < 512
            int q = f >> 6;
            int h = f & 63;
            float hval = g_h2[((size_t)q * N_NODES + m) * 64 + h];
#pragma unroll
            for (int c = 0; c < NCLS; c++)
                acc[c] += hval * sW2t[c * (RP * EMB) + f];
        }
#pragma unroll
        for (int off = 16; off > 0; off >>= 1) {
#pragma unroll
            for (int c = 0; c < NCLS; c++)
                acc[c] += __shfl_xor_sync(0xffffffffu, acc[c], off);
        }
        if (lane < NCLS)
            out[(size_t)m * NCLS + lane] = acc[lane] + b2[lane];
    }
}

// ---------------- launch ----------------
extern "C" void kernel_launch(void* const* d_in, const int* in_sizes, int n_in,
                              void* d_out, int out_size) {
    const float* rm    = (const float*)d_in[0];   // relation_matrix (NT, 64)
    const int*   hrow  = (const int*)d_in[1];     // s tiled
    // d_in[2] = hcol (derivable: o*r), d_in[3] = vrow (derivable: s*r) — unused
    const int*   vcol  = (const int*)d_in[4];     // o tiled
    const float* Wl1   = (const float*)d_in[5];
    const float* bl1   = (const float*)d_in[6];
    const float* Wl2   = (const float*)d_in[7];
    const float* bl2   = (const float*)d_in[8];
    const float* w1    = (const float*)d_in[9];   // weights1 (8, 20000, 64)
    const float* w2    = (const float*)d_in[10];  // weights2 (8, 64, 16)
    const float* bias1 = (const float*)d_in[11];
    const float* bias2 = (const float*)d_in[12];
    float* out = (float*)d_out;

    k_zero<<<2048, 256>>>();
    k_phaseA<<<2048, 256>>>(rm, hrow, vcol, Wl1, bl1, Wl2, bl2);
    k_scan<<<1, 512>>>();
    k_fill<<<(NT + 255) / 256, 256>>>(hrow);
    k_h<<<2500, 256>>>(vcol, w1, bias1);
    k_h2<<<2500, 256>>>(vcol);
    k_logits<<<2048, 256>>>(w2, bias2, out);
}

// round 6
// speedup vs baseline: 1.6628x; 1.5807x over previous
#include <cuda_runtime.h>
#include <math.h>

#define N_NODES 20000
#define RP 8
#define EMB 64
#define NCLS 16
#define NT 250000
#define NRP (N_NODES * RP)
#define NRELS 64

// ---------------- scratch (static device globals; no allocation) ----------------
__device__ __align__(16) float g_l1[(size_t)NT * RP];          //  8 MB  l1[t][r] (later normalized)
__device__ __align__(16) float g_l2[(size_t)NT * RP];          //  8 MB  l2[t][r] (later normalized)
__device__ __align__(16) float g_colsum[NRP];                  // 640 KB
__device__ __align__(16) float g_rowsum[NRP];                  // 640 KB
__device__ __align__(16) float g_h[(size_t)N_NODES * EMB];     //  5 MB
__device__ __align__(16) int   g_cnt[N_NODES];
__device__ __align__(16) int   g_cur[N_NODES];
__device__ __align__(16) int   g_offs[N_NODES + 1];
__device__ __align__(16) int   g_csr[NT];

// ---------------- kernel 0: init (zero sums/counters, out = bias2 tiled) ----------------
__global__ void k_init(float* __restrict__ out, const float* __restrict__ b2) {
    int tid = blockIdx.x * blockDim.x + threadIdx.x;
    int stride = gridDim.x * blockDim.x;
    float b[NCLS];
#pragma unroll
    for (int c = 0; c < NCLS; c++) b[c] = b2[c];
    for (int i = tid; i < NRP; i += stride) { g_colsum[i] = 0.f; g_rowsum[i] = 0.f; }
    for (int i = tid; i < N_NODES; i += stride) { g_cnt[i] = 0; g_cur[i] = 0; }
    for (int i = tid; i < N_NODES * NCLS; i += stride) out[i] = b[i & 15];
}

// ---------------- kernel 1: l1, l2(softmax), colsum, rowsum, per-s counts ----------------
// Tile of 128 triples' relation rows staged in smem (stride 66, conflict-free).
// Thread = (triple, layer); computes all 8 r outputs with plain FMAs. No shuffles.
#define TPB_A 128
__global__ void k_phaseA(const float* __restrict__ rm,
                         const int* __restrict__ hrow,
                         const int* __restrict__ vcol,
                         const float* __restrict__ Wl1, const float* __restrict__ bl1,
                         const float* __restrict__ Wl2, const float* __restrict__ bl2) {
    __shared__ float smRM[TPB_A * 66];          // 128 rows, stride 66 floats
    __shared__ float sW1[NRELS * RP];           // [k][r]
    __shared__ float sW2[NRELS * RP];
    __shared__ float sb1[RP], sb2[RP];
    __shared__ float s_cs0, s_rs0;

    int tid = threadIdx.x;                      // 256 threads
    for (int i = tid; i < NRELS * RP; i += 256) { sW1[i] = Wl1[i]; sW2[i] = Wl2[i]; }
    if (tid < RP) { sb1[tid] = bl1[tid]; sb2[tid] = bl2[tid]; }
    if (tid == 0) { s_cs0 = 0.f; s_rs0 = 0.f; }

    int t0 = blockIdx.x * TPB_A;
    // stage 128x64 rm rows as float2, smem stride 66 (banks = (2*row + k) % 32, conflict-free)
    for (int i = tid; i < TPB_A * 32; i += 256) {
        int row = i >> 5;
        int c2 = i & 31;
        int t = t0 + row;
        float2 v = (t < NT) ? *(const float2*)&rm[(size_t)t * 64 + c2 * 2]
                            : make_float2(0.f, 0.f);
        *(float2*)&smRM[row * 66 + c2 * 2] = v;
    }
    __syncthreads();

    int tl = tid >> 1;          // local triple 0..127
    int layer = tid & 1;
    int t = t0 + tl;
    float cs0 = 0.f, rs0 = 0.f;

    if (t < NT) {
        const float* sW = layer ? sW2 : sW1;
        float a[8];
#pragma unroll
        for (int r = 0; r < 8; r++) a[r] = 0.f;
        const float* rmrow = &smRM[tl * 66];
#pragma unroll 8
        for (int k = 0; k < 64; k++) {
            float x = rmrow[k];
            const float4 w0 = *(const float4*)&sW[k * 8];
            const float4 w1 = *(const float4*)&sW[k * 8 + 4];
            a[0] += x * w0.x; a[1] += x * w0.y; a[2] += x * w0.z; a[3] += x * w0.w;
            a[4] += x * w1.x; a[5] += x * w1.y; a[6] += x * w1.z; a[7] += x * w1.w;
        }
        if (layer == 0) {
            // l1 = a + b1; colsum scatter (r>=1), r=0 to block acc
            int o = vcol[t];
#pragma unroll
            for (int r = 0; r < 8; r++) a[r] += sb1[r];
            *(float4*)&g_l1[(size_t)t * 8]     = make_float4(a[0], a[1], a[2], a[3]);
            *(float4*)&g_l1[(size_t)t * 8 + 4] = make_float4(a[4], a[5], a[6], a[7]);
            cs0 = a[0];
#pragma unroll
            for (int r = 1; r < 8; r++) atomicAdd(&g_colsum[o * r], a[r]);
        } else {
            // l2 = softmax(a + b2); rowsum scatter; histogram
            int s = hrow[t];
            float m = -1e30f;
#pragma unroll
            for (int r = 0; r < 8; r++) { a[r] += sb2[r]; m = fmaxf(m, a[r]); }
            float ssum = 0.f;
#pragma unroll
            for (int r = 0; r < 8; r++) { a[r] = expf(a[r] - m); ssum += a[r]; }
            float inv = 1.f / ssum;
#pragma unroll
            for (int r = 0; r < 8; r++) a[r] *= inv;
            *(float4*)&g_l2[(size_t)t * 8]     = make_float4(a[0], a[1], a[2], a[3]);
            *(float4*)&g_l2[(size_t)t * 8 + 4] = make_float4(a[4], a[5], a[6], a[7]);
            rs0 = a[0];
#pragma unroll
            for (int r = 1; r < 8; r++) atomicAdd(&g_rowsum[s * r], a[r]);
            atomicAdd(&g_cnt[s], 1);
        }
    }
    // reduce r=0 contributions within block
#pragma unroll
    for (int off = 16; off > 0; off >>= 1) {
        cs0 += __shfl_xor_sync(0xffffffffu, cs0, off);
        rs0 += __shfl_xor_sync(0xffffffffu, rs0, off);
    }
    if ((tid & 31) == 0) { atomicAdd(&s_cs0, cs0); atomicAdd(&s_rs0, rs0); }
    __syncthreads();
    if (tid == 0) {
        atomicAdd(&g_colsum[0], s_cs0);
        atomicAdd(&g_rowsum[0], s_rs0);
    }
}

// ---------------- kernel 1.5: exclusive scan of g_cnt -> g_offs ----------------
__global__ void k_scan() {
    __shared__ int part[512];
    const int CH = (N_NODES + 511) / 512;
    int tid = threadIdx.x;
    int base = tid * CH;
    int sum = 0;
    for (int i = 0; i < CH; i++) {
        int idx = base + i;
        if (idx < N_NODES) sum += g_cnt[idx];
    }
    part[tid] = sum;
    __syncthreads();
    for (int off = 1; off < 512; off <<= 1) {
        int v = (tid >= off) ? part[tid - off] : 0;
        __syncthreads();
        part[tid] += v;
        __syncthreads();
    }
    int run = (tid == 0) ? 0 : part[tid - 1];
    for (int i = 0; i < CH; i++) {
        int idx = base + i;
        if (idx < N_NODES) { g_offs[idx] = run; run += g_cnt[idx]; }
    }
    if (tid == 0) g_offs[N_NODES] = NT;
}

// ---------------- kernel 1.6: fill CSR ----------------
__global__ void k_fill(const int* __restrict__ hrow) {
    int t = blockIdx.x * blockDim.x + threadIdx.x;
    if (t < NT) {
        int s = hrow[t];
        int pos = g_offs[s] + atomicAdd(&g_cur[s], 1);
        g_csr[pos] = t;
    }
}

// ---------------- kernel 1.7: normalize l1, l2 in a flat throughput pass ----------------
// thread = (t, r); scattered colsum/rowsum gathers with 2M-way parallelism.
__global__ void k_norm(const int* __restrict__ hrow, const int* __restrict__ vcol) {
    int gid = blockIdx.x * blockDim.x + threadIdx.x;
    if (gid >= NT * 8) return;
    int t = gid >> 3;
    int r = gid & 7;
    int o = __ldg(&vcol[t]);
    int s = __ldg(&hrow[t]);
    g_l1[gid] = g_l1[gid] / g_colsum[o * r];
    g_l2[gid] = g_l2[gid] / fmaxf(g_rowsum[s * r], 1e-6f);
}

// ---------------- kernel 2: h[s] = relu(bias1 + sum over s's triples) ----------------
// One warp per node; normalized l1 loaded coalesced; t/o prefetched 1 deep.
__global__ void k_h(const int* __restrict__ vcol,
                    const float* __restrict__ W1,
                    const float* __restrict__ bias1) {
    int tid = threadIdx.x;
    int lane = tid & 31;
    int warpId = blockIdx.x * (blockDim.x >> 5) + (tid >> 5);
    int nwarps = gridDim.x * (blockDim.x >> 5);

    const float2 w0v = *(const float2*)&W1[lane * 2];     // flat row 0 (r=0)
    const float2 bv  = *(const float2*)&bias1[lane * 2];

    for (int s = warpId; s < N_NODES; s += nwarps) {
        int beg = g_offs[s], end = g_offs[s + 1];
        float accx = 0.f, accy = 0.f, w0sum = 0.f;
        int t = 0, o = 0;
        if (beg < end) { t = g_csr[beg]; o = __ldg(&vcol[t]); }
        for (int j = beg; j < end; j++) {
            int tn = 0, on = 0;
            if (j + 1 < end) { tn = g_csr[j + 1]; on = __ldg(&vcol[tn]); }
            float w = (lane < 8) ? g_l1[(size_t)t * 8 + lane] : 0.f;
            w0sum += __shfl_sync(0xffffffffu, w, 0);
#pragma unroll
            for (int r = 1; r < 8; r++) {
                float wr = __shfl_sync(0xffffffffu, w, r);
                const float2 wv = *(const float2*)&W1[(size_t)(o * r) * 64 + lane * 2];
                accx += wr * wv.x;
                accy += wr * wv.y;
            }
            t = tn; o = on;
        }
        accx += w0sum * w0v.x;
        accy += w0sum * w0v.y;
        float2 outv = make_float2(fmaxf(accx + bv.x, 0.f), fmaxf(accy + bv.y, 0.f));
        *(float2*)&g_h[(size_t)s * 64 + lane * 2] = outv;
    }
}

// ---------------- kernel 3: fused h2 + logits ----------------
// One warp per node s: accumulate the 8 r-slices over s's triples in registers,
// stage to smem, contract each slice with W2[q_v] (q_v = s*r / N), atomically
// add the 16 class values into out[n_v] (n_v = s*r % N). r=0 (row 0 for every
// node) accumulates in block-shared and flushes once per block.
#define TPB_F 128   // 4 warps
__global__ void k_h2logits(const int* __restrict__ vcol,
                           const float* __restrict__ W2,
                           float* __restrict__ out) {
    __shared__ float sW2t[EMB * RP * NCLS];      // [h][q][c], 32 KB, conflict-free
    __shared__ float sA[4][RP * EMB];            // per-warp staged slices, 8 KB
    __shared__ float blockAcc[NCLS];

    int tid = threadIdx.x;
    for (int i = tid; i < RP * EMB * NCLS; i += TPB_F) {
        int q = i >> 10;            // i / (64*16)
        int h = (i >> 4) & 63;
        int c = i & 15;
        sW2t[h * (RP * NCLS) + q * NCLS + c] = W2[i];
    }
    if (tid < NCLS) blockAcc[tid] = 0.f;
    __syncthreads();

    int lane = tid & 31;
    int wrp = tid >> 5;
    int warpId = blockIdx.x * 4 + wrp;
    int nwarps = gridDim.x * 4;
    float* myA = sA[wrp];

    for (int s = warpId; s < N_NODES; s += nwarps) {
        int beg = g_offs[s], end = g_offs[s + 1];
        if (beg == end) continue;

        float ax[8], ay[8];
#pragma unroll
        for (int r = 0; r < 8; r++) { ax[r] = 0.f; ay[r] = 0.f; }

        int t = g_csr[beg], o = __ldg(&vcol[t]);
        for (int j = beg; j < end; j++) {
            int tn = 0, on = 0;
            if (j + 1 < end) { tn = g_csr[j + 1]; on = __ldg(&vcol[tn]); }
            float2 hv = *(const float2*)&g_h[(size_t)o * 64 + lane * 2];
            float lr = (lane < 8) ? g_l2[(size_t)t * 8 + lane] : 0.f;
#pragma unroll
            for (int r = 0; r < 8; r++) {
                float w = __shfl_sync(0xffffffffu, lr, r);
                ax[r] += w * hv.x;
                ay[r] += w * hv.y;
            }
            t = tn; o = on;
        }
        // stage slices
#pragma unroll
        for (int r = 0; r < 8; r++) {
            myA[r * 64 + lane * 2]     = ax[r];
            myA[r * 64 + lane * 2 + 1] = ay[r];
        }
        __syncwarp();

        // contract: 128 (r,c) pairs over 32 lanes, 4 per lane; c = lane & 15 fixed
        int c = lane & 15;
#pragma unroll
        for (int i = 0; i < 4; i++) {
            int p = lane + 32 * i;
            int r = p >> 4;
            int v = s * r;
            int q = v / N_NODES;
            int nv = v - q * N_NODES;
            const float* arow = &myA[r * 64];
            const float* wcol = &sW2t[q * NCLS + c];
            float dot = 0.f;
#pragma unroll 8
            for (int h = 0; h < 64; h++)
                dot += arow[h] * wcol[h * (RP * NCLS)];
            if (r == 0)
                atomicAdd(&blockAcc[c], dot);
            else
                atomicAdd(&out[(size_t)nv * NCLS + c], dot);
        }
        __syncwarp();
    }
    __syncthreads();
    if (tid < NCLS) atomicAdd(&out[tid], blockAcc[tid]);
}

// ---------------- launch ----------------
extern "C" void kernel_launch(void* const* d_in, const int* in_sizes, int n_in,
                              void* d_out, int out_size) {
    const float* rm    = (const float*)d_in[0];   // relation_matrix (NT, 64)
    const int*   hrow  = (const int*)d_in[1];     // s tiled
    const int*   vcol  = (const int*)d_in[4];     // o tiled
    const float* Wl1   = (const float*)d_in[5];
    const float* bl1   = (const float*)d_in[6];
    const float* Wl2   = (const float*)d_in[7];
    const float* bl2   = (const float*)d_in[8];
    const float* w1    = (const float*)d_in[9];   // weights1 (8, 20000, 64)
    const float* w2    = (const float*)d_in[10];  // weights2 (8, 64, 16)
    const float* bias1 = (const float*)d_in[11];
    const float* bias2 = (const float*)d_in[12];
    float* out = (float*)d_out;

    k_init<<<512, 256>>>(out, bias2);
    k_phaseA<<<(NT + TPB_A - 1) / TPB_A, 256>>>(rm, hrow, vcol, Wl1, bl1, Wl2, bl2);
    k_scan<<<1, 512>>>();
    k_fill<<<(NT + 255) / 256, 256>>>(hrow);
    k_norm<<<(NT * 8 + 255) / 256, 256>>>(hrow, vcol);
    k_h<<<2500, 256>>>(vcol, w1, bias1);
    k_h2logits<<<1250, TPB_F>>>(vcol, w2, out);
}

// round 7
// speedup vs baseline: 1.9754x; 1.1880x over previous
#include <cuda_runtime.h>
#include <math.h>

#define N_NODES 20000
#define RP 8
#define EMB 64
#define NCLS 16
#define NT 250000
#define NRP (N_NODES * RP)
#define NRELS 64
#define FULLM 0xffffffffu

// ---------------- scratch (static device globals; no allocation) ----------------
__device__ __align__(16) float g_l1[(size_t)NT * RP];          //  8 MB  l1[t][r]
__device__ __align__(16) float g_l2[(size_t)NT * RP];          //  8 MB  l2[t][r] (softmax'd)
__device__ __align__(16) float g_colsum[NRP];                  // 640 KB (becomes reciprocal)
__device__ __align__(16) float g_rowsum[NRP];                  // 640 KB (becomes reciprocal)
__device__ __align__(16) float g_h[(size_t)N_NODES * EMB];     //  5 MB
__device__ __align__(16) int   g_cnt[N_NODES];
__device__ __align__(16) int   g_cur[N_NODES];
__device__ __align__(16) int   g_offs[N_NODES + 1];
__device__ __align__(16) int   g_csr[NT];

// ---------------- kernel 0: init (zero sums/counters, out = bias2 tiled) ----------------
__global__ void k_init(float* __restrict__ out, const float* __restrict__ b2) {
    int tid = blockIdx.x * blockDim.x + threadIdx.x;
    int stride = gridDim.x * blockDim.x;
    float b[NCLS];
#pragma unroll
    for (int c = 0; c < NCLS; c++) b[c] = b2[c];
    for (int i = tid; i < NRP; i += stride) { g_colsum[i] = 0.f; g_rowsum[i] = 0.f; }
    for (int i = tid; i < N_NODES; i += stride) { g_cnt[i] = 0; g_cur[i] = 0; }
    for (int i = tid; i < N_NODES * NCLS; i += stride) out[i] = b[i & 15];
}

// ---------------- kernel 1: l1, l2(softmax), colsum, rowsum, per-s counts ----------------
// Tile of 128 triples' relation rows staged in smem (stride 66, conflict-free).
// Thread = (triple, layer); all-FMA inner loop, no shuffles.
#define TPB_A 128
__global__ void k_phaseA(const float* __restrict__ rm,
                         const int* __restrict__ hrow,
                         const int* __restrict__ vcol,
                         const float* __restrict__ Wl1, const float* __restrict__ bl1,
                         const float* __restrict__ Wl2, const float* __restrict__ bl2) {
    __shared__ float smRM[TPB_A * 66];
    __shared__ float sW1[NRELS * RP];
    __shared__ float sW2[NRELS * RP];
    __shared__ float sb1[RP], sb2[RP];
    __shared__ float s_cs0, s_rs0;

    int tid = threadIdx.x;                      // 256 threads
    for (int i = tid; i < NRELS * RP; i += 256) { sW1[i] = Wl1[i]; sW2[i] = Wl2[i]; }
    if (tid < RP) { sb1[tid] = bl1[tid]; sb2[tid] = bl2[tid]; }
    if (tid == 0) { s_cs0 = 0.f; s_rs0 = 0.f; }

    int t0 = blockIdx.x * TPB_A;
    for (int i = tid; i < TPB_A * 32; i += 256) {
        int row = i >> 5;
        int c2 = i & 31;
        int t = t0 + row;
        float2 v = (t < NT) ? *(const float2*)&rm[(size_t)t * 64 + c2 * 2]
                            : make_float2(0.f, 0.f);
        *(float2*)&smRM[row * 66 + c2 * 2] = v;
    }
    __syncthreads();

    int tl = tid >> 1;
    int layer = tid & 1;
    int t = t0 + tl;
    float cs0 = 0.f, rs0 = 0.f;

    if (t < NT) {
        const float* sW = layer ? sW2 : sW1;
        float a[8];
#pragma unroll
        for (int r = 0; r < 8; r++) a[r] = 0.f;
        const float* rmrow = &smRM[tl * 66];
#pragma unroll 8
        for (int k = 0; k < 64; k++) {
            float x = rmrow[k];
            const float4 w0 = *(const float4*)&sW[k * 8];
            const float4 w1 = *(const float4*)&sW[k * 8 + 4];
            a[0] += x * w0.x; a[1] += x * w0.y; a[2] += x * w0.z; a[3] += x * w0.w;
            a[4] += x * w1.x; a[5] += x * w1.y; a[6] += x * w1.z; a[7] += x * w1.w;
        }
        if (layer == 0) {
            int o = vcol[t];
#pragma unroll
            for (int r = 0; r < 8; r++) a[r] += sb1[r];
            *(float4*)&g_l1[(size_t)t * 8]     = make_float4(a[0], a[1], a[2], a[3]);
            *(float4*)&g_l1[(size_t)t * 8 + 4] = make_float4(a[4], a[5], a[6], a[7]);
            cs0 = a[0];
#pragma unroll
            for (int r = 1; r < 8; r++) atomicAdd(&g_colsum[o * r], a[r]);
        } else {
            int s = hrow[t];
            float m = -1e30f;
#pragma unroll
            for (int r = 0; r < 8; r++) { a[r] += sb2[r]; m = fmaxf(m, a[r]); }
            float ssum = 0.f;
#pragma unroll
            for (int r = 0; r < 8; r++) { a[r] = expf(a[r] - m); ssum += a[r]; }
            float inv = 1.f / ssum;
#pragma unroll
            for (int r = 0; r < 8; r++) a[r] *= inv;
            *(float4*)&g_l2[(size_t)t * 8]     = make_float4(a[0], a[1], a[2], a[3]);
            *(float4*)&g_l2[(size_t)t * 8 + 4] = make_float4(a[4], a[5], a[6], a[7]);
            rs0 = a[0];
#pragma unroll
            for (int r = 1; r < 8; r++) atomicAdd(&g_rowsum[s * r], a[r]);
            atomicAdd(&g_cnt[s], 1);
        }
    }
#pragma unroll
    for (int off = 16; off > 0; off >>= 1) {
        cs0 += __shfl_xor_sync(FULLM, cs0, off);
        rs0 += __shfl_xor_sync(FULLM, rs0, off);
    }
    if ((tid & 31) == 0) { atomicAdd(&s_cs0, cs0); atomicAdd(&s_rs0, rs0); }
    __syncthreads();
    if (tid == 0) {
        atomicAdd(&g_colsum[0], s_cs0);
        atomicAdd(&g_rowsum[0], s_rs0);
    }
}

// ---------------- kernel 1.5: exclusive scan of g_cnt -> g_offs ----------------
__global__ void k_scan() {
    __shared__ int part[512];
    const int CH = (N_NODES + 511) / 512;
    int tid = threadIdx.x;
    int base = tid * CH;
    int sum = 0;
    for (int i = 0; i < CH; i++) {
        int idx = base + i;
        if (idx < N_NODES) sum += g_cnt[idx];
    }
    part[tid] = sum;
    __syncthreads();
    for (int off = 1; off < 512; off <<= 1) {
        int v = (tid >= off) ? part[tid - off] : 0;
        __syncthreads();
        part[tid] += v;
        __syncthreads();
    }
    int run = (tid == 0) ? 0 : part[tid - 1];
    for (int i = 0; i < CH; i++) {
        int idx = base + i;
        if (idx < N_NODES) { g_offs[idx] = run; run += g_cnt[idx]; }
    }
    if (tid == 0) g_offs[N_NODES] = NT;
}

// ---------------- kernel 1.6: fill CSR + reciprocals of colsum/rowsum ----------------
__global__ void k_fill(const int* __restrict__ hrow) {
    int gid = blockIdx.x * blockDim.x + threadIdx.x;
    if (gid < NRP) {
        g_colsum[gid] = 1.f / g_colsum[gid];
        g_rowsum[gid] = 1.f / fmaxf(g_rowsum[gid], 1e-6f);
    }
    if (gid < NT) {
        int s = hrow[gid];
        int pos = g_offs[s] + atomicAdd(&g_cur[s], 1);
        g_csr[pos] = gid;
    }
}

// ---------------- kernel 2: h[s] = relu(bias1 + sum over s's triples) ----------------
// Warp processes 2 triples/iter: half-warp (16 lanes) per triple, float4 lanes.
__global__ void k_h(const int* __restrict__ vcol,
                    const float* __restrict__ W1,
                    const float* __restrict__ bias1) {
    int tid = threadIdx.x;
    int lane = tid & 31;
    int hl = lane & 15;
    int half = lane >> 4;
    int warpId = blockIdx.x * (blockDim.x >> 5) + (tid >> 5);
    int nwarps = gridDim.x * (blockDim.x >> 5);

    const float4 w0v = *(const float4*)&W1[hl * 4];       // flat row 0 (r=0)
    const float4 bv  = *(const float4*)&bias1[hl * 4];

    for (int s = warpId; s < N_NODES; s += nwarps) {
        int beg = g_offs[s], end = g_offs[s + 1];
        float4 acc = make_float4(0.f, 0.f, 0.f, 0.f);
        float w0sum = 0.f;

        int t0v = -1, t1v = -1, o0v = 0, o1v = 0;
        if (beg < end)     { t0v = g_csr[beg];     o0v = __ldg(&vcol[t0v]); }
        if (beg + 1 < end) { t1v = g_csr[beg + 1]; o1v = __ldg(&vcol[t1v]); }

        for (int j = beg; j < end; j += 2) {
            int nt0 = -1, nt1 = -1, no0 = 0, no1 = 0;
            if (j + 2 < end) { nt0 = g_csr[j + 2]; no0 = __ldg(&vcol[nt0]); }
            if (j + 3 < end) { nt1 = g_csr[j + 3]; no1 = __ldg(&vcol[nt1]); }

            int th = half ? t1v : t0v;
            int oh = half ? o1v : o0v;
            float w = 0.f;
            if (hl < 8 && th >= 0)
                w = g_l1[(size_t)th * 8 + hl] * g_colsum[oh * hl];  // hl=0 -> recip colsum[0]
            w0sum += __shfl_sync(FULLM, w, 0, 16);
#pragma unroll
            for (int r = 1; r < 8; r++) {
                float wr = __shfl_sync(FULLM, w, r, 16);
                const float4 wv = *(const float4*)&W1[(size_t)(oh * r) * 64 + hl * 4];
                acc.x += wr * wv.x; acc.y += wr * wv.y;
                acc.z += wr * wv.z; acc.w += wr * wv.w;
            }
            t0v = nt0; t1v = nt1; o0v = no0; o1v = no1;
        }
        // combine the two halves
        acc.x += __shfl_xor_sync(FULLM, acc.x, 16);
        acc.y += __shfl_xor_sync(FULLM, acc.y, 16);
        acc.z += __shfl_xor_sync(FULLM, acc.z, 16);
        acc.w += __shfl_xor_sync(FULLM, acc.w, 16);
        w0sum += __shfl_xor_sync(FULLM, w0sum, 16);
        if (lane < 16) {
            float4 outv;
            outv.x = fmaxf(acc.x + w0sum * w0v.x + bv.x, 0.f);
            outv.y = fmaxf(acc.y + w0sum * w0v.y + bv.y, 0.f);
            outv.z = fmaxf(acc.z + w0sum * w0v.z + bv.z, 0.f);
            outv.w = fmaxf(acc.w + w0sum * w0v.w + bv.w, 0.f);
            *(float4*)&g_h[(size_t)s * 64 + lane * 4] = outv;
        }
    }
}

// ---------------- kernel 3: fused h2 + logits ----------------
// Half-warp per triple, float4 h[o] gather; combine halves at node end, stage
// to smem, contract each r-slice with W2[q_v] and atomically add 16 class
// values into out[n_v] where (q_v, n_v) = divmod(s*r, N). r=0 goes to
// block-shared accumulator flushed once per block.
#define TPB_F 128   // 4 warps
__global__ void k_h2logits(const int* __restrict__ vcol,
                           const float* __restrict__ W2,
                           float* __restrict__ out) {
    __shared__ float sW2t[EMB * RP * NCLS];      // [h][q][c], 32 KB
    __shared__ float sA[4][RP * EMB];            // per-warp staged slices
    __shared__ float blockAcc[NCLS];

    int tid = threadIdx.x;
    for (int i = tid; i < RP * EMB * NCLS; i += TPB_F) {
        int q = i >> 10;
        int h = (i >> 4) & 63;
        int c = i & 15;
        sW2t[h * (RP * NCLS) + q * NCLS + c] = W2[i];
    }
    if (tid < NCLS) blockAcc[tid] = 0.f;
    __syncthreads();

    int lane = tid & 31;
    int hl = lane & 15;
    int half = lane >> 4;
    int wrp = tid >> 5;
    int warpId = blockIdx.x * 4 + wrp;
    int nwarps = gridDim.x * 4;
    float* myA = sA[wrp];

    for (int s = warpId; s < N_NODES; s += nwarps) {
        int beg = g_offs[s], end = g_offs[s + 1];
        if (beg == end) continue;

        // reciprocal rowsum for this node (hl=0 -> recip rowsum[0], correct for r=0)
        float rinv = (hl < 8) ? g_rowsum[(size_t)s * hl] : 0.f;

        float4 ar[8];
#pragma unroll
        for (int r = 0; r < 8; r++) ar[r] = make_float4(0.f, 0.f, 0.f, 0.f);

        int t0v = -1, t1v = -1, o0v = 0, o1v = 0;
        t0v = g_csr[beg]; o0v = __ldg(&vcol[t0v]);
        if (beg + 1 < end) { t1v = g_csr[beg + 1]; o1v = __ldg(&vcol[t1v]); }

        for (int j = beg; j < end; j += 2) {
            int nt0 = -1, nt1 = -1, no0 = 0, no1 = 0;
            if (j + 2 < end) { nt0 = g_csr[j + 2]; no0 = __ldg(&vcol[nt0]); }
            if (j + 3 < end) { nt1 = g_csr[j + 3]; no1 = __ldg(&vcol[nt1]); }

            int th = half ? t1v : t0v;
            int oh = half ? o1v : o0v;
            float4 hv = *(const float4*)&g_h[(size_t)oh * 64 + hl * 4];
            float w = 0.f;
            if (hl < 8 && th >= 0)
                w = g_l2[(size_t)th * 8 + hl] * rinv;
#pragma unroll
            for (int r = 0; r < 8; r++) {
                float wr = __shfl_sync(FULLM, w, r, 16);
                ar[r].x += wr * hv.x; ar[r].y += wr * hv.y;
                ar[r].z += wr * hv.z; ar[r].w += wr * hv.w;
            }
            t0v = nt0; t1v = nt1; o0v = no0; o1v = no1;
        }
        // combine halves and stage
#pragma unroll
        for (int r = 0; r < 8; r++) {
            ar[r].x += __shfl_xor_sync(FULLM, ar[r].x, 16);
            ar[r].y += __shfl_xor_sync(FULLM, ar[r].y, 16);
            ar[r].z += __shfl_xor_sync(FULLM, ar[r].z, 16);
            ar[r].w += __shfl_xor_sync(FULLM, ar[r].w, 16);
        }
        if (lane < 16) {
#pragma unroll
            for (int r = 0; r < 8; r++)
                *(float4*)&myA[r * 64 + lane * 4] = ar[r];
        }
        __syncwarp();

        // contract: 128 (r,c) pairs over 32 lanes, 4 per lane; c = lane & 15 fixed
        int c = lane & 15;
#pragma unroll
        for (int i = 0; i < 4; i++) {
            int p = lane + 32 * i;
            int r = p >> 4;
            int v = s * r;
            int q = v / N_NODES;
            int nv = v - q * N_NODES;
            const float* arow = &myA[r * 64];
            const float* wcol = &sW2t[q * NCLS + c];
            float dot = 0.f;
#pragma unroll 8
            for (int h = 0; h < 64; h++)
                dot += arow[h] * wcol[h * (RP * NCLS)];
            if (r == 0)
                atomicAdd(&blockAcc[c], dot);
            else
                atomicAdd(&out[(size_t)nv * NCLS + c], dot);
        }
        __syncwarp();
    }
    __syncthreads();
    if (tid < NCLS) atomicAdd(&out[tid], blockAcc[tid]);
}

// ---------------- launch ----------------
extern "C" void kernel_launch(void* const* d_in, const int* in_sizes, int n_in,
                              void* d_out, int out_size) {
    const float* rm    = (const float*)d_in[0];   // relation_matrix (NT, 64)
    const int*   hrow  = (const int*)d_in[1];     // s tiled
    const int*   vcol  = (const int*)d_in[4];     // o tiled
    const float* Wl1   = (const float*)d_in[5];
    const float* bl1   = (const float*)d_in[6];
    const float* Wl2   = (const float*)d_in[7];
    const float* bl2   = (const float*)d_in[8];
    const float* w1    = (const float*)d_in[9];   // weights1 (8, 20000, 64)
    const float* w2    = (const float*)d_in[10];  // weights2 (8, 64, 16)
    const float* bias1 = (const float*)d_in[11];
    const float* bias2 = (const float*)d_in[12];
    float* out = (float*)d_out;

    k_init<<<512, 256>>>(out, bias2);
    k_phaseA<<<(NT + TPB_A - 1) / TPB_A, 256>>>(rm, hrow, vcol, Wl1, bl1, Wl2, bl2);
    k_scan<<<1, 512>>>();
    k_fill<<<(NT + 255) / 256, 256>>>(hrow);
    k_h<<<2500, 256>>>(vcol, w1, bias1);
    k_h2logits<<<1250, TPB_F>>>(vcol, w2, out);
}

// round 8
// speedup vs baseline: 2.1237x; 1.0751x over previous
#include <cuda_runtime.h>
#include <math.h>

#define N_NODES 20000
#define RP 8
#define EMB 64
#define NCLS 16
#define NT 250000
#define NRP (N_NODES * RP)
#define NRELS 64
#define FULLM 0xffffffffu

// ---------------- scratch (static device globals; no allocation) ----------------
__device__ __align__(16) float g_l1[(size_t)NT * RP];          //  8 MB  l1[t][r]
__device__ __align__(16) float g_l2[(size_t)NT * RP];          //  8 MB  l2[t][r] (softmax'd)
__device__ __align__(16) float g_colsum[NRP];                  // 640 KB
__device__ __align__(16) float g_rowsum[NRP];                  // 640 KB
__device__ __align__(16) float g_h[(size_t)N_NODES * EMB];     //  5 MB
__device__ __align__(16) int   g_offs[N_NODES + 1];            // segment starts (hrow sorted!)

// ---------------- kernel 0: init ----------------
// zero colsum/rowsum, out = bias2 tiled, and build g_offs from the SORTED hrow
// (pairs came from np.unique -> lexicographic order, so hrow[0:NT] ascending).
__global__ void k_init(float* __restrict__ out, const float* __restrict__ b2,
                       const int* __restrict__ hrow) {
    int tid = blockIdx.x * blockDim.x + threadIdx.x;
    int stride = gridDim.x * blockDim.x;
    float b[NCLS];
#pragma unroll
    for (int c = 0; c < NCLS; c++) b[c] = b2[c];
    for (int i = tid; i < NRP; i += stride) { g_colsum[i] = 0.f; g_rowsum[i] = 0.f; }
    for (int i = tid; i < N_NODES * NCLS; i += stride) out[i] = b[i & 15];
    // boundary detect: offs[s] = first t with hrow[t] >= s
    for (int t = tid; t < NT; t += stride) {
        int sc = hrow[t];
        int sp = (t == 0) ? -1 : hrow[t - 1];
        for (int s = sp + 1; s <= sc; s++) g_offs[s] = t;
        if (t == NT - 1)
            for (int s = sc + 1; s <= N_NODES; s++) g_offs[s] = NT;
    }
}

// ---------------- kernel 1: l1, l2(softmax), colsum, rowsum ----------------
// Tile of 128 triples' relation rows staged in smem (stride 66, conflict-free).
// Thread = (triple, layer); all-FMA inner loop, no shuffles.
#define TPB_A 128
__global__ void k_phaseA(const float* __restrict__ rm,
                         const int* __restrict__ hrow,
                         const int* __restrict__ vcol,
                         const float* __restrict__ Wl1, const float* __restrict__ bl1,
                         const float* __restrict__ Wl2, const float* __restrict__ bl2) {
    __shared__ float smRM[TPB_A * 66];
    __shared__ float sW1[NRELS * RP];
    __shared__ float sW2[NRELS * RP];
    __shared__ float sb1[RP], sb2[RP];
    __shared__ float s_cs0, s_rs0;

    int tid = threadIdx.x;                      // 256 threads
    for (int i = tid; i < NRELS * RP; i += 256) { sW1[i] = Wl1[i]; sW2[i] = Wl2[i]; }
    if (tid < RP) { sb1[tid] = bl1[tid]; sb2[tid] = bl2[tid]; }
    if (tid == 0) { s_cs0 = 0.f; s_rs0 = 0.f; }

    int t0 = blockIdx.x * TPB_A;
    for (int i = tid; i < TPB_A * 32; i += 256) {
        int row = i >> 5;
        int c2 = i & 31;
        int t = t0 + row;
        float2 v = (t < NT) ? *(const float2*)&rm[(size_t)t * 64 + c2 * 2]
                            : make_float2(0.f, 0.f);
        *(float2*)&smRM[row * 66 + c2 * 2] = v;
    }
    __syncthreads();

    int tl = tid >> 1;
    int layer = tid & 1;
    int t = t0 + tl;
    float cs0 = 0.f, rs0 = 0.f;

    if (t < NT) {
        const float* sW = layer ? sW2 : sW1;
        float a[8];
#pragma unroll
        for (int r = 0; r < 8; r++) a[r] = 0.f;
        const float* rmrow = &smRM[tl * 66];
#pragma unroll 8
        for (int k = 0; k < 64; k++) {
            float x = rmrow[k];
            const float4 w0 = *(const float4*)&sW[k * 8];
            const float4 w1 = *(const float4*)&sW[k * 8 + 4];
            a[0] += x * w0.x; a[1] += x * w0.y; a[2] += x * w0.z; a[3] += x * w0.w;
            a[4] += x * w1.x; a[5] += x * w1.y; a[6] += x * w1.z; a[7] += x * w1.w;
        }
        if (layer == 0) {
            int o = vcol[t];
#pragma unroll
            for (int r = 0; r < 8; r++) a[r] += sb1[r];
            *(float4*)&g_l1[(size_t)t * 8]     = make_float4(a[0], a[1], a[2], a[3]);
            *(float4*)&g_l1[(size_t)t * 8 + 4] = make_float4(a[4], a[5], a[6], a[7]);
            cs0 = a[0];
#pragma unroll
            for (int r = 1; r < 8; r++) atomicAdd(&g_colsum[o * r], a[r]);
        } else {
            int s = hrow[t];
            float m = -1e30f;
#pragma unroll
            for (int r = 0; r < 8; r++) { a[r] += sb2[r]; m = fmaxf(m, a[r]); }
            float ssum = 0.f;
#pragma unroll
            for (int r = 0; r < 8; r++) { a[r] = expf(a[r] - m); ssum += a[r]; }
            float inv = 1.f / ssum;
#pragma unroll
            for (int r = 0; r < 8; r++) a[r] *= inv;
            *(float4*)&g_l2[(size_t)t * 8]     = make_float4(a[0], a[1], a[2], a[3]);
            *(float4*)&g_l2[(size_t)t * 8 + 4] = make_float4(a[4], a[5], a[6], a[7]);
            rs0 = a[0];
#pragma unroll
            for (int r = 1; r < 8; r++) atomicAdd(&g_rowsum[s * r], a[r]);
        }
    }
#pragma unroll
    for (int off = 16; off > 0; off >>= 1) {
        cs0 += __shfl_xor_sync(FULLM, cs0, off);
        rs0 += __shfl_xor_sync(FULLM, rs0, off);
    }
    if ((tid & 31) == 0) { atomicAdd(&s_cs0, cs0); atomicAdd(&s_rs0, rs0); }
    __syncthreads();
    if (tid == 0) {
        atomicAdd(&g_colsum[0], s_cs0);
        atomicAdd(&g_rowsum[0], s_rs0);
    }
}

// ---------------- kernel 2: h[s] = relu(bias1 + sum over s's triples) ----------------
// Triples sorted by s -> t = j directly. Half-warp per triple, float4 lanes.
__global__ void k_h(const int* __restrict__ vcol,
                    const float* __restrict__ W1,
                    const float* __restrict__ bias1) {
    int tid = threadIdx.x;
    int lane = tid & 31;
    int hl = lane & 15;
    int half = lane >> 4;
    int warpId = blockIdx.x * (blockDim.x >> 5) + (tid >> 5);
    int nwarps = gridDim.x * (blockDim.x >> 5);

    const float4 w0v = *(const float4*)&W1[hl * 4];       // flat row 0 (r=0)
    const float4 bv  = *(const float4*)&bias1[hl * 4];

    for (int s = warpId; s < N_NODES; s += nwarps) {
        int beg = g_offs[s], end = g_offs[s + 1];
        float4 acc = make_float4(0.f, 0.f, 0.f, 0.f);
        float w0sum = 0.f;

        for (int j = beg; j < end; j += 2) {
            int th = j + half;
            bool valid = th < end;
            int oh = valid ? __ldg(&vcol[th]) : 0;
            float w = 0.f;
            if (hl < 8 && valid)
                w = g_l1[(size_t)th * 8 + hl] / g_colsum[oh * hl]; // hl=0 -> colsum[0]
            w0sum += __shfl_sync(FULLM, w, 0, 16);
#pragma unroll
            for (int r = 1; r < 8; r++) {
                float wr = __shfl_sync(FULLM, w, r, 16);
                const float4 wv = *(const float4*)&W1[(size_t)(oh * r) * 64 + hl * 4];
                acc.x += wr * wv.x; acc.y += wr * wv.y;
                acc.z += wr * wv.z; acc.w += wr * wv.w;
            }
        }
        // combine the two halves
        acc.x += __shfl_xor_sync(FULLM, acc.x, 16);
        acc.y += __shfl_xor_sync(FULLM, acc.y, 16);
        acc.z += __shfl_xor_sync(FULLM, acc.z, 16);
        acc.w += __shfl_xor_sync(FULLM, acc.w, 16);
        w0sum += __shfl_xor_sync(FULLM, w0sum, 16);
        if (lane < 16) {
            float4 outv;
            outv.x = fmaxf(acc.x + w0sum * w0v.x + bv.x, 0.f);
            outv.y = fmaxf(acc.y + w0sum * w0v.y + bv.y, 0.f);
            outv.z = fmaxf(acc.z + w0sum * w0v.z + bv.z, 0.f);
            outv.w = fmaxf(acc.w + w0sum * w0v.w + bv.w, 0.f);
            *(float4*)&g_h[(size_t)s * 64 + lane * 4] = outv;
        }
    }
}

// ---------------- kernel 3: fused h2 + logits ----------------
// Half-warp per triple (t = j), float4 h[o] gather; combine halves at node end,
// stage to smem, contract each r-slice with W2[q_v], atomically add 16 class
// values into out[n_v] where (q_v, n_v) = divmod(s*r, N). r=0 goes to
// block-shared accumulator flushed once per block.
#define TPB_F 128   // 4 warps
__global__ void k_h2logits(const int* __restrict__ vcol,
                           const float* __restrict__ W2,
                           float* __restrict__ out) {
    __shared__ float sW2t[EMB * RP * NCLS];      // [h][q][c], 32 KB
    __shared__ float sA[4][RP * EMB];            // per-warp staged slices
    __shared__ float blockAcc[NCLS];

    int tid = threadIdx.x;
    for (int i = tid; i < RP * EMB * NCLS; i += TPB_F) {
        int q = i >> 10;
        int h = (i >> 4) & 63;
        int c = i & 15;
        sW2t[h * (RP * NCLS) + q * NCLS + c] = W2[i];
    }
    if (tid < NCLS) blockAcc[tid] = 0.f;
    __syncthreads();

    int lane = tid & 31;
    int hl = lane & 15;
    int half = lane >> 4;
    int wrp = tid >> 5;
    int warpId = blockIdx.x * 4 + wrp;
    int nwarps = gridDim.x * 4;
    float* myA = sA[wrp];

    for (int s = warpId; s < N_NODES; s += nwarps) {
        int beg = g_offs[s], end = g_offs[s + 1];
        if (beg == end) continue;

        // reciprocal rowsum for this node (hl=0 -> rowsum[0], correct for r=0)
        float rinv = (hl < 8) ? 1.f / fmaxf(g_rowsum[(size_t)s * hl], 1e-6f) : 0.f;

        float4 ar[8];
#pragma unroll
        for (int r = 0; r < 8; r++) ar[r] = make_float4(0.f, 0.f, 0.f, 0.f);

        for (int j = beg; j < end; j += 2) {
            int th = j + half;
            bool valid = th < end;
            int oh = valid ? __ldg(&vcol[th]) : 0;
            float4 hv = *(const float4*)&g_h[(size_t)oh * 64 + hl * 4];
            float w = 0.f;
            if (hl < 8 && valid)
                w = g_l2[(size_t)th * 8 + hl] * rinv;
#pragma unroll
            for (int r = 0; r < 8; r++) {
                float wr = __shfl_sync(FULLM, w, r, 16);
                ar[r].x += wr * hv.x; ar[r].y += wr * hv.y;
                ar[r].z += wr * hv.z; ar[r].w += wr * hv.w;
            }
        }
        // combine halves and stage
#pragma unroll
        for (int r = 0; r < 8; r++) {
            ar[r].x += __shfl_xor_sync(FULLM, ar[r].x, 16);
            ar[r].y += __shfl_xor_sync(FULLM, ar[r].y, 16);
            ar[r].z += __shfl_xor_sync(FULLM, ar[r].z, 16);
            ar[r].w += __shfl_xor_sync(FULLM, ar[r].w, 16);
        }
        if (lane < 16) {
#pragma unroll
            for (int r = 0; r < 8; r++)
                *(float4*)&myA[r * 64 + lane * 4] = ar[r];
        }
        __syncwarp();

        // contract: 128 (r,c) pairs over 32 lanes, 4 per lane; c = lane & 15 fixed
        int c = lane & 15;
#pragma unroll
        for (int i = 0; i < 4; i++) {
            int p = lane + 32 * i;
            int r = p >> 4;
            int v = s * r;
            int q = v / N_NODES;
            int nv = v - q * N_NODES;
            const float* arow = &myA[r * 64];
            const float* wcol = &sW2t[q * NCLS + c];
            float dot = 0.f;
#pragma unroll 8
            for (int h = 0; h < 64; h++)
                dot += arow[h] * wcol[h * (RP * NCLS)];
            if (r == 0)
                atomicAdd(&blockAcc[c], dot);
            else
                atomicAdd(&out[(size_t)nv * NCLS + c], dot);
        }
        __syncwarp();
    }
    __syncthreads();
    if (tid < NCLS) atomicAdd(&out[tid], blockAcc[tid]);
}

// ---------------- launch ----------------
extern "C" void kernel_launch(void* const* d_in, const int* in_sizes, int n_in,
                              void* d_out, int out_size) {
    const float* rm    = (const float*)d_in[0];   // relation_matrix (NT, 64)
    const int*   hrow  = (const int*)d_in[1];     // s tiled (sorted ascending for t<NT)
    const int*   vcol  = (const int*)d_in[4];     // o tiled
    const float* Wl1   = (const float*)d_in[5];
    const float* bl1   = (const float*)d_in[6];
    const float* Wl2   = (const float*)d_in[7];
    const float* bl2   = (const float*)d_in[8];
    const float* w1    = (const float*)d_in[9];   // weights1 (8, 20000, 64)
    const float* w2    = (const float*)d_in[10];  // weights2 (8, 64, 16)
    const float* bias1 = (const float*)d_in[11];
    const float* bias2 = (const float*)d_in[12];
    float* out = (float*)d_out;

    k_init<<<1024, 256>>>(out, bias2, hrow);
    k_phaseA<<<(NT + TPB_A - 1) / TPB_A, 256>>>(rm, hrow, vcol, Wl1, bl1, Wl2, bl2);
    k_h<<<2500, 256>>>(vcol, w1, bias1);
    k_h2logits<<<1250, TPB_F>>>(vcol, w2, out);
}

// round 9
// speedup vs baseline: 2.1688x; 1.0212x over previous
#include <cuda_runtime.h>
#include <math.h>

#define N_NODES 20000
#define RP 8
#define EMB 64
#define NCLS 16
#define NT 250000
#define NRP (N_NODES * RP)
#define NRELS 64
#define FULLM 0xffffffffu

// ---------------- scratch (static device globals; no allocation) ----------------
__device__ __align__(16) float g_l1[(size_t)NT * RP];          //  8 MB  l1[t][r]
__device__ __align__(16) float g_l2[(size_t)NT * RP];          //  8 MB  l2[t][r] (softmax'd)
__device__ __align__(16) float g_colsum[NRP];                  // 640 KB
__device__ __align__(16) float g_rowsum[NRP];                  // 640 KB
__device__ __align__(16) float g_h[(size_t)N_NODES * EMB];     //  5 MB
__device__ __align__(16) int   g_offs[N_NODES + 1];            // segment starts (hrow sorted)

// ---------------- kernel 0: init ----------------
__global__ void k_init(float* __restrict__ out, const float* __restrict__ b2,
                       const int* __restrict__ hrow) {
    int tid = blockIdx.x * blockDim.x + threadIdx.x;
    int stride = gridDim.x * blockDim.x;
    float b[NCLS];
#pragma unroll
    for (int c = 0; c < NCLS; c++) b[c] = b2[c];
    for (int i = tid; i < NRP; i += stride) { g_colsum[i] = 0.f; g_rowsum[i] = 0.f; }
    for (int i = tid; i < N_NODES * NCLS; i += stride) out[i] = b[i & 15];
    // boundary detect: offs[s] = first t with hrow[t] >= s (hrow sorted ascending)
    for (int t = tid; t < NT; t += stride) {
        int sc = hrow[t];
        int sp = (t == 0) ? -1 : hrow[t - 1];
        for (int s = sp + 1; s <= sc; s++) g_offs[s] = t;
        if (t == NT - 1)
            for (int s = sc + 1; s <= N_NODES; s++) g_offs[s] = NT;
    }
}

// ---------------- kernel 1: l1, l2(softmax), colsum, rowsum ----------------
#define TPB_A 128
__global__ void k_phaseA(const float* __restrict__ rm,
                         const int* __restrict__ hrow,
                         const int* __restrict__ vcol,
                         const float* __restrict__ Wl1, const float* __restrict__ bl1,
                         const float* __restrict__ Wl2, const float* __restrict__ bl2) {
    __shared__ float smRM[TPB_A * 66];
    __shared__ float sW1[NRELS * RP];
    __shared__ float sW2[NRELS * RP];
    __shared__ float sb1[RP], sb2[RP];
    __shared__ float s_cs0, s_rs0;

    int tid = threadIdx.x;                      // 256 threads
    for (int i = tid; i < NRELS * RP; i += 256) { sW1[i] = Wl1[i]; sW2[i] = Wl2[i]; }
    if (tid < RP) { sb1[tid] = bl1[tid]; sb2[tid] = bl2[tid]; }
    if (tid == 0) { s_cs0 = 0.f; s_rs0 = 0.f; }

    int t0 = blockIdx.x * TPB_A;
    for (int i = tid; i < TPB_A * 32; i += 256) {
        int row = i >> 5;
        int c2 = i & 31;
        int t = t0 + row;
        float2 v = (t < NT) ? *(const float2*)&rm[(size_t)t * 64 + c2 * 2]
                            : make_float2(0.f, 0.f);
        *(float2*)&smRM[row * 66 + c2 * 2] = v;
    }
    __syncthreads();

    int tl = tid >> 1;
    int layer = tid & 1;
    int t = t0 + tl;
    float cs0 = 0.f, rs0 = 0.f;

    if (t < NT) {
        const float* sW = layer ? sW2 : sW1;
        float a[8];
#pragma unroll
        for (int r = 0; r < 8; r++) a[r] = 0.f;
        const float* rmrow = &smRM[tl * 66];
#pragma unroll 8
        for (int k = 0; k < 64; k++) {
            float x = rmrow[k];
            const float4 w0 = *(const float4*)&sW[k * 8];
            const float4 w1 = *(const float4*)&sW[k * 8 + 4];
            a[0] += x * w0.x; a[1] += x * w0.y; a[2] += x * w0.z; a[3] += x * w0.w;
            a[4] += x * w1.x; a[5] += x * w1.y; a[6] += x * w1.z; a[7] += x * w1.w;
        }
        if (layer == 0) {
            int o = vcol[t];
#pragma unroll
            for (int r = 0; r < 8; r++) a[r] += sb1[r];
            *(float4*)&g_l1[(size_t)t * 8]     = make_float4(a[0], a[1], a[2], a[3]);
            *(float4*)&g_l1[(size_t)t * 8 + 4] = make_float4(a[4], a[5], a[6], a[7]);
            cs0 = a[0];
#pragma unroll
            for (int r = 1; r < 8; r++) atomicAdd(&g_colsum[o * r], a[r]);
        } else {
            int s = hrow[t];
            float m = -1e30f;
#pragma unroll
            for (int r = 0; r < 8; r++) { a[r] += sb2[r]; m = fmaxf(m, a[r]); }
            float ssum = 0.f;
#pragma unroll
            for (int r = 0; r < 8; r++) { a[r] = expf(a[r] - m); ssum += a[r]; }
            float inv = 1.f / ssum;
#pragma unroll
            for (int r = 0; r < 8; r++) a[r] *= inv;
            *(float4*)&g_l2[(size_t)t * 8]     = make_float4(a[0], a[1], a[2], a[3]);
            *(float4*)&g_l2[(size_t)t * 8 + 4] = make_float4(a[4], a[5], a[6], a[7]);
            rs0 = a[0];
#pragma unroll
            for (int r = 1; r < 8; r++) atomicAdd(&g_rowsum[s * r], a[r]);
        }
    }
#pragma unroll
    for (int off = 16; off > 0; off >>= 1) {
        cs0 += __shfl_xor_sync(FULLM, cs0, off);
        rs0 += __shfl_xor_sync(FULLM, rs0, off);
    }
    if ((tid & 31) == 0) { atomicAdd(&s_cs0, cs0); atomicAdd(&s_rs0, rs0); }
    __syncthreads();
    if (tid == 0) {
        atomicAdd(&g_colsum[0], s_cs0);
        atomicAdd(&g_rowsum[0], s_rs0);
    }
}

// ---------------- kernel 2: h[s] = relu(bias1 + sum over s's triples) ----------------
__global__ void k_h(const int* __restrict__ vcol,
                    const float* __restrict__ W1,
                    const float* __restrict__ bias1) {
    int tid = threadIdx.x;
    int lane = tid & 31;
    int hl = lane & 15;
    int half = lane >> 4;
    int warpId = blockIdx.x * (blockDim.x >> 5) + (tid >> 5);
    int nwarps = gridDim.x * (blockDim.x >> 5);

    const float4 w0v = *(const float4*)&W1[hl * 4];       // flat row 0 (r=0)
    const float4 bv  = *(const float4*)&bias1[hl * 4];

    for (int s = warpId; s < N_NODES; s += nwarps) {
        int beg = g_offs[s], end = g_offs[s + 1];
        float4 acc = make_float4(0.f, 0.f, 0.f, 0.f);
        float w0sum = 0.f;

        for (int j = beg; j < end; j += 2) {
            int th = j + half;
            bool valid = th < end;
            int oh = valid ? __ldg(&vcol[th]) : 0;
            float w = 0.f;
            if (hl < 8 && valid)
                w = g_l1[(size_t)th * 8 + hl] / g_colsum[oh * hl];
            w0sum += __shfl_sync(FULLM, w, 0, 16);
#pragma unroll
            for (int r = 1; r < 8; r++) {
                float wr = __shfl_sync(FULLM, w, r, 16);
                const float4 wv = *(const float4*)&W1[(size_t)(oh * r) * 64 + hl * 4];
                acc.x += wr * wv.x; acc.y += wr * wv.y;
                acc.z += wr * wv.z; acc.w += wr * wv.w;
            }
        }
        acc.x += __shfl_xor_sync(FULLM, acc.x, 16);
        acc.y += __shfl_xor_sync(FULLM, acc.y, 16);
        acc.z += __shfl_xor_sync(FULLM, acc.z, 16);
        acc.w += __shfl_xor_sync(FULLM, acc.w, 16);
        w0sum += __shfl_xor_sync(FULLM, w0sum, 16);
        if (lane < 16) {
            float4 outv;
            outv.x = fmaxf(acc.x + w0sum * w0v.x + bv.x, 0.f);
            outv.y = fmaxf(acc.y + w0sum * w0v.y + bv.y, 0.f);
            outv.z = fmaxf(acc.z + w0sum * w0v.z + bv.z, 0.f);
            outv.w = fmaxf(acc.w + w0sum * w0v.w + bv.w, 0.f);
            *(float4*)&g_h[(size_t)s * 64 + lane * 4] = outv;
        }
    }
}

// ---------------- kernel 3: fused h2 + logits ----------------
// Half-warp per triple (t = j); per node: accumulate 8 r-slices in registers,
// combine halves. r=0 slice accumulates ACROSS nodes per warp (all nodes' r=0
// targets h2 row 0), contracted once per warp at kernel end. r=1..7 slices
// staged to smem, contracted with vectorized conflict-free W2 (float4 groups),
// results atomically added into out.
#define TPB_F 256   // 8 warps
__global__ void k_h2logits(const int* __restrict__ vcol,
                           const float* __restrict__ W2,
                           float* __restrict__ out) {
    __shared__ float4 sW2v[RP * 16 * NCLS];      // [(q*16+k)*16+c] = (W2[q][4k+j][c])_j, 32 KB
    __shared__ float  sA[8][7 * EMB];            // per-warp staged r=1..7 slices, 14 KB
    __shared__ float  blockAcc[NCLS];

    int tid = threadIdx.x;
    for (int i = tid; i < RP * 16 * NCLS; i += TPB_F) {
        int q = i >> 8;
        int k = (i >> 4) & 15;
        int c = i & 15;
        sW2v[i] = make_float4(W2[q * 1024 + (4 * k + 0) * 16 + c],
                              W2[q * 1024 + (4 * k + 1) * 16 + c],
                              W2[q * 1024 + (4 * k + 2) * 16 + c],
                              W2[q * 1024 + (4 * k + 3) * 16 + c]);
    }
    if (tid < NCLS) blockAcc[tid] = 0.f;
    __syncthreads();

    int lane = tid & 31;
    int hl = lane & 15;
    int half = lane >> 4;
    int wrp = tid >> 5;
    int warpId = blockIdx.x * 8 + wrp;
    int nwarps = gridDim.x * 8;
    float* myA = sA[wrp];

    float4 wa0 = make_float4(0.f, 0.f, 0.f, 0.f);   // r=0 slice, summed over this warp's nodes

    for (int s = warpId; s < N_NODES; s += nwarps) {
        int beg = g_offs[s], end = g_offs[s + 1];
        if (beg == end) continue;

        float rinv = (hl < 8) ? 1.f / fmaxf(g_rowsum[(size_t)s * hl], 1e-6f) : 0.f;

        float4 ar[8];
#pragma unroll
        for (int r = 0; r < 8; r++) ar[r] = make_float4(0.f, 0.f, 0.f, 0.f);

        for (int j = beg; j < end; j += 2) {
            int th = j + half;
            bool valid = th < end;
            int oh = valid ? __ldg(&vcol[th]) : 0;
            float4 hv = *(const float4*)&g_h[(size_t)oh * 64 + hl * 4];
            float w = 0.f;
            if (hl < 8 && valid)
                w = g_l2[(size_t)th * 8 + hl] * rinv;
#pragma unroll
            for (int r = 0; r < 8; r++) {
                float wr = __shfl_sync(FULLM, w, r, 16);
                ar[r].x += wr * hv.x; ar[r].y += wr * hv.y;
                ar[r].z += wr * hv.z; ar[r].w += wr * hv.w;
            }
        }
        // combine halves
#pragma unroll
        for (int r = 0; r < 8; r++) {
            ar[r].x += __shfl_xor_sync(FULLM, ar[r].x, 16);
            ar[r].y += __shfl_xor_sync(FULLM, ar[r].y, 16);
            ar[r].z += __shfl_xor_sync(FULLM, ar[r].z, 16);
            ar[r].w += __shfl_xor_sync(FULLM, ar[r].w, 16);
        }
        // r=0 accumulates across nodes (targets h2 row 0 always)
        wa0.x += ar[0].x; wa0.y += ar[0].y; wa0.z += ar[0].z; wa0.w += ar[0].w;

        __syncwarp();   // prior contraction reads (previous node) done before overwrite
        if (lane < 16) {
#pragma unroll
            for (int r = 1; r < 8; r++)
                *(float4*)&myA[(r - 1) * 64 + lane * 4] = ar[r];
        }
        __syncwarp();

        // contraction: 112 (r,c) pairs, r = 1..7; c = lane & 15
        int c = lane & 15;
#pragma unroll
        for (int i = 0; i < 4; i++) {
            int p = lane + 32 * i;
            if (p < 112) {
                int r = 1 + (p >> 4);
                int v = s * r;
                int q = v / N_NODES;
                int nv = v - q * N_NODES;
                const float4* arow4 = (const float4*)&myA[(r - 1) * 64];
                const float4* w4 = &sW2v[(q * 16) * 16 + c];
                float dot = 0.f;
#pragma unroll
                for (int k = 0; k < 16; k++) {
                    float4 a = arow4[k];
                    float4 w = w4[k * 16];
                    dot += a.x * w.x + a.y * w.y + a.z * w.z + a.w * w.w;
                }
                atomicAdd(&out[(size_t)nv * NCLS + c], dot);
            }
        }
        __syncwarp();
    }

    // flush this warp's r=0 accumulation: stage, contract with W2[q=0], add to blockAcc
    __syncwarp();
    if (lane < 16) *(float4*)&myA[lane * 4] = wa0;
    __syncwarp();
    if (lane < 16) {
        int c = lane;
        const float4* arow4 = (const float4*)myA;
        const float4* w4 = &sW2v[c];
        float dot = 0.f;
#pragma unroll
        for (int k = 0; k < 16; k++) {
            float4 a = arow4[k];
            float4 w = w4[k * 16];
            dot += a.x * w.x + a.y * w.y + a.z * w.z + a.w * w.w;
        }
        atomicAdd(&blockAcc[c], dot);
    }
    __syncthreads();
    if (tid < NCLS) atomicAdd(&out[tid], blockAcc[tid]);
}

// ---------------- launch ----------------
extern "C" void kernel_launch(void* const* d_in, const int* in_sizes, int n_in,
                              void* d_out, int out_size) {
    const float* rm    = (const float*)d_in[0];   // relation_matrix (NT, 64)
    const int*   hrow  = (const int*)d_in[1];     // s tiled (sorted ascending for t<NT)
    const int*   vcol  = (const int*)d_in[4];     // o tiled
    const float* Wl1   = (const float*)d_in[5];
    const float* bl1   = (const float*)d_in[6];
    const float* Wl2   = (const float*)d_in[7];
    const float* bl2   = (const float*)d_in[8];
    const float* w1    = (const float*)d_in[9];   // weights1 (8, 20000, 64)
    const float* w2    = (const float*)d_in[10];  // weights2 (8, 64, 16)
    const float* bias1 = (const float*)d_in[11];
    const float* bias2 = (const float*)d_in[12];
    float* out = (float*)d_out;

    k_init<<<1024, 256>>>(out, bias2, hrow);
    k_phaseA<<<(NT + TPB_A - 1) / TPB_A, 256>>>(rm, hrow, vcol, Wl1, bl1, Wl2, bl2);
    k_h<<<2500, 256>>>(vcol, w1, bias1);
    k_h2logits<<<592, TPB_F>>>(vcol, w2, out);
}

// round 10
// speedup vs baseline: 2.2312x; 1.0288x over previous
#include <cuda_runtime.h>
#include <math.h>

#define N_NODES 20000
#define RP 8
#define EMB 64
#define NCLS 16
#define NT 250000
#define NRP (N_NODES * RP)
#define NRELS 64
#define FULLM 0xffffffffu

// ---------------- scratch (static device globals; no allocation) ----------------
__device__ __align__(16) float g_l1[(size_t)NT * RP];          //  8 MB  l1[t][r]
__device__ __align__(16) float g_l2[(size_t)NT * RP];          //  8 MB  l2[t][r] (softmax'd)
__device__ __align__(16) float g_colsum[NRP];                  // 640 KB (-> reciprocals)
__device__ __align__(16) float g_rowsum[NRP];                  // 640 KB (-> reciprocals)
__device__ __align__(16) float g_h[(size_t)N_NODES * EMB];     //  5 MB
__device__ __align__(16) int   g_offs[N_NODES + 1];            // segment starts (hrow sorted)

// ---------------- kernel 0: init ----------------
__global__ void k_init(float* __restrict__ out, const float* __restrict__ b2,
                       const int* __restrict__ hrow) {
    int tid = blockIdx.x * blockDim.x + threadIdx.x;
    int stride = gridDim.x * blockDim.x;
    float b[NCLS];
#pragma unroll
    for (int c = 0; c < NCLS; c++) b[c] = b2[c];
    for (int i = tid; i < NRP; i += stride) { g_colsum[i] = 0.f; g_rowsum[i] = 0.f; }
    for (int i = tid; i < N_NODES * NCLS; i += stride) out[i] = b[i & 15];
    // boundary detect: offs[s] = first t with hrow[t] >= s (hrow sorted ascending)
    for (int t = tid; t < NT; t += stride) {
        int sc = hrow[t];
        int sp = (t == 0) ? -1 : hrow[t - 1];
        for (int s = sp + 1; s <= sc; s++) g_offs[s] = t;
        if (t == NT - 1)
            for (int s = sc + 1; s <= N_NODES; s++) g_offs[s] = NT;
    }
}

// ---------------- kernel 1: l1, l2(softmax), colsum, rowsum ----------------
#define TPB_A 128
__global__ void k_phaseA(const float* __restrict__ rm,
                         const int* __restrict__ hrow,
                         const int* __restrict__ vcol,
                         const float* __restrict__ Wl1, const float* __restrict__ bl1,
                         const float* __restrict__ Wl2, const float* __restrict__ bl2) {
    __shared__ float smRM[TPB_A * 66];
    __shared__ float sW1[NRELS * RP];
    __shared__ float sW2[NRELS * RP];
    __shared__ float sb1[RP], sb2[RP];
    __shared__ float s_cs0, s_rs0;

    int tid = threadIdx.x;                      // 256 threads
    for (int i = tid; i < NRELS * RP; i += 256) { sW1[i] = Wl1[i]; sW2[i] = Wl2[i]; }
    if (tid < RP) { sb1[tid] = bl1[tid]; sb2[tid] = bl2[tid]; }
    if (tid == 0) { s_cs0 = 0.f; s_rs0 = 0.f; }

    int t0 = blockIdx.x * TPB_A;
    for (int i = tid; i < TPB_A * 32; i += 256) {
        int row = i >> 5;
        int c2 = i & 31;
        int t = t0 + row;
        float2 v = (t < NT) ? *(const float2*)&rm[(size_t)t * 64 + c2 * 2]
                            : make_float2(0.f, 0.f);
        *(float2*)&smRM[row * 66 + c2 * 2] = v;
    }
    __syncthreads();

    int tl = tid >> 1;
    int layer = tid & 1;
    int t = t0 + tl;
    float cs0 = 0.f, rs0 = 0.f;

    if (t < NT) {
        const float* sW = layer ? sW2 : sW1;
        float a[8];
#pragma unroll
        for (int r = 0; r < 8; r++) a[r] = 0.f;
        const float* rmrow = &smRM[tl * 66];
#pragma unroll 8
        for (int k = 0; k < 64; k++) {
            float x = rmrow[k];
            const float4 w0 = *(const float4*)&sW[k * 8];
            const float4 w1 = *(const float4*)&sW[k * 8 + 4];
            a[0] += x * w0.x; a[1] += x * w0.y; a[2] += x * w0.z; a[3] += x * w0.w;
            a[4] += x * w1.x; a[5] += x * w1.y; a[6] += x * w1.z; a[7] += x * w1.w;
        }
        if (layer == 0) {
            int o = vcol[t];
#pragma unroll
            for (int r = 0; r < 8; r++) a[r] += sb1[r];
            *(float4*)&g_l1[(size_t)t * 8]     = make_float4(a[0], a[1], a[2], a[3]);
            *(float4*)&g_l1[(size_t)t * 8 + 4] = make_float4(a[4], a[5], a[6], a[7]);
            cs0 = a[0];
#pragma unroll
            for (int r = 1; r < 8; r++) atomicAdd(&g_colsum[o * r], a[r]);
        } else {
            int s = hrow[t];
            float m = -1e30f;
#pragma unroll
            for (int r = 0; r < 8; r++) { a[r] += sb2[r]; m = fmaxf(m, a[r]); }
            float ssum = 0.f;
#pragma unroll
            for (int r = 0; r < 8; r++) { a[r] = expf(a[r] - m); ssum += a[r]; }
            float inv = 1.f / ssum;
#pragma unroll
            for (int r = 0; r < 8; r++) a[r] *= inv;
            *(float4*)&g_l2[(size_t)t * 8]     = make_float4(a[0], a[1], a[2], a[3]);
            *(float4*)&g_l2[(size_t)t * 8 + 4] = make_float4(a[4], a[5], a[6], a[7]);
            rs0 = a[0];
#pragma unroll
            for (int r = 1; r < 8; r++) atomicAdd(&g_rowsum[s * r], a[r]);
        }
    }
#pragma unroll
    for (int off = 16; off > 0; off >>= 1) {
        cs0 += __shfl_xor_sync(FULLM, cs0, off);
        rs0 += __shfl_xor_sync(FULLM, rs0, off);
    }
    if ((tid & 31) == 0) { atomicAdd(&s_cs0, cs0); atomicAdd(&s_rs0, rs0); }
    __syncthreads();
    if (tid == 0) {
        atomicAdd(&g_colsum[0], s_cs0);
        atomicAdd(&g_rowsum[0], s_rs0);
    }
}

// ---------------- kernel 1.5: reciprocals in place ----------------
__global__ void k_recip() {
    int i = blockIdx.x * blockDim.x + threadIdx.x;
    if (i < NRP) {
        g_colsum[i] = 1.f / g_colsum[i];
        g_rowsum[i] = 1.f / fmaxf(g_rowsum[i], 1e-6f);
    }
}

// ---------------- kernel 2: h[s] = relu(bias1 + sum over s's triples) ----------------
// Half-warp per triple (t = j sorted). Broadcast float4 l1 loads + broadcast
// colsum-recip scalars; NO shuffles / divides in the inner loop.
__global__ void __launch_bounds__(256) k_h(const int* __restrict__ vcol,
                                           const float* __restrict__ W1,
                                           const float* __restrict__ bias1) {
    int tid = threadIdx.x;
    int lane = tid & 31;
    int hl = lane & 15;
    int half = lane >> 4;
    int warpId = blockIdx.x * (blockDim.x >> 5) + (tid >> 5);
    int nwarps = gridDim.x * (blockDim.x >> 5);

    const float4 w0v = *(const float4*)&W1[hl * 4];       // flat row 0 (r=0)
    const float4 bv  = *(const float4*)&bias1[hl * 4];
    const float cs0r = g_colsum[0];                       // recip of colsum[0]

    for (int s = warpId; s < N_NODES; s += nwarps) {
        int beg = g_offs[s], end = g_offs[s + 1];
        float4 acc = make_float4(0.f, 0.f, 0.f, 0.f);
        float w0sum = 0.f;

        int oh = (beg + half < end) ? __ldg(&vcol[beg + half]) : 0;

        for (int j = beg; j < end; j += 2) {
            int th = j + half;
            bool valid = th < end;
            int ohn = (th + 2 < end) ? __ldg(&vcol[th + 2]) : 0;   // prefetch

            float4 wA = make_float4(0.f, 0.f, 0.f, 0.f), wB = wA;
            if (valid) {
                wA = *(const float4*)&g_l1[(size_t)th * 8];
                wB = *(const float4*)&g_l1[(size_t)th * 8 + 4];
            }
            // colsum reciprocals for r=1..7 (broadcast scalar loads)
            float c1 = __ldg(&g_colsum[oh]);
            float c2 = __ldg(&g_colsum[oh * 2]);
            float c3 = __ldg(&g_colsum[oh * 3]);
            float c4 = __ldg(&g_colsum[oh * 4]);
            float c5 = __ldg(&g_colsum[oh * 5]);
            float c6 = __ldg(&g_colsum[oh * 6]);
            float c7 = __ldg(&g_colsum[oh * 7]);

            w0sum += wA.x * cs0r;
            float w1 = wA.y * c1, w2 = wA.z * c2, w3 = wA.w * c3;
            float w4 = wB.x * c4, w5 = wB.y * c5, w6 = wB.z * c6, w7 = wB.w * c7;

            const float4 v1 = *(const float4*)&W1[(size_t)(oh)     * 64 + hl * 4];
            const float4 v2 = *(const float4*)&W1[(size_t)(oh * 2) * 64 + hl * 4];
            const float4 v3 = *(const float4*)&W1[(size_t)(oh * 3) * 64 + hl * 4];
            const float4 v4 = *(const float4*)&W1[(size_t)(oh * 4) * 64 + hl * 4];
            const float4 v5 = *(const float4*)&W1[(size_t)(oh * 5) * 64 + hl * 4];
            const float4 v6 = *(const float4*)&W1[(size_t)(oh * 6) * 64 + hl * 4];
            const float4 v7 = *(const float4*)&W1[(size_t)(oh * 7) * 64 + hl * 4];

            acc.x += w1 * v1.x + w2 * v2.x + w3 * v3.x + w4 * v4.x
                   + w5 * v5.x + w6 * v6.x + w7 * v7.x;
            acc.y += w1 * v1.y + w2 * v2.y + w3 * v3.y + w4 * v4.y
                   + w5 * v5.y + w6 * v6.y + w7 * v7.y;
            acc.z += w1 * v1.z + w2 * v2.z + w3 * v3.z + w4 * v4.z
                   + w5 * v5.z + w6 * v6.z + w7 * v7.z;
            acc.w += w1 * v1.w + w2 * v2.w + w3 * v3.w + w4 * v4.w
                   + w5 * v5.w + w6 * v6.w + w7 * v7.w;

            oh = ohn;
        }
        // combine halves
        acc.x += __shfl_xor_sync(FULLM, acc.x, 16);
        acc.y += __shfl_xor_sync(FULLM, acc.y, 16);
        acc.z += __shfl_xor_sync(FULLM, acc.z, 16);
        acc.w += __shfl_xor_sync(FULLM, acc.w, 16);
        w0sum += __shfl_xor_sync(FULLM, w0sum, 16);
        if (lane < 16) {
            float4 outv;
            outv.x = fmaxf(acc.x + w0sum * w0v.x + bv.x, 0.f);
            outv.y = fmaxf(acc.y + w0sum * w0v.y + bv.y, 0.f);
            outv.z = fmaxf(acc.z + w0sum * w0v.z + bv.z, 0.f);
            outv.w = fmaxf(acc.w + w0sum * w0v.w + bv.w, 0.f);
            *(float4*)&g_h[(size_t)s * 64 + lane * 4] = outv;
        }
    }
}

// ---------------- kernel 3: fused h2 + logits ----------------
// Half-warp per triple; per node preload 8 rowsum recips (broadcast); per
// triple 2 broadcast l2 float4 loads + 1 hv gather — NO shuffles in the loop.
// r=0 slice accumulates across the warp's nodes, contracted once at the end.
#define TPB_F 256   // 8 warps
__global__ void __launch_bounds__(TPB_F, 3) k_h2logits(const int* __restrict__ vcol,
                                                       const float* __restrict__ W2,
                                                       float* __restrict__ out) {
    __shared__ float4 sW2v[RP * 16 * NCLS];      // [(q*16+k)*16+c], 32 KB
    __shared__ float  sA[8][7 * EMB];            // per-warp staged r=1..7 slices, 14 KB
    __shared__ float  blockAcc[NCLS];

    int tid = threadIdx.x;
    for (int i = tid; i < RP * 16 * NCLS; i += TPB_F) {
        int q = i >> 8;
        int k = (i >> 4) & 15;
        int c = i & 15;
        sW2v[i] = make_float4(W2[q * 1024 + (4 * k + 0) * 16 + c],
                              W2[q * 1024 + (4 * k + 1) * 16 + c],
                              W2[q * 1024 + (4 * k + 2) * 16 + c],
                              W2[q * 1024 + (4 * k + 3) * 16 + c]);
    }
    if (tid < NCLS) blockAcc[tid] = 0.f;
    __syncthreads();

    int lane = tid & 31;
    int hl = lane & 15;
    int half = lane >> 4;
    int wrp = tid >> 5;
    int warpId = blockIdx.x * 8 + wrp;
    int nwarps = gridDim.x * 8;
    float* myA = sA[wrp];

    float4 wa0 = make_float4(0.f, 0.f, 0.f, 0.f);   // r=0 slice over this warp's nodes

    for (int s = warpId; s < N_NODES; s += nwarps) {
        int beg = g_offs[s], end = g_offs[s + 1];
        if (beg == end) continue;

        // rowsum reciprocals for this node (broadcast; index s*r, r=0 -> [0])
        float rv[8];
#pragma unroll
        for (int r = 0; r < 8; r++) rv[r] = __ldg(&g_rowsum[(size_t)s * r]);

        float4 ar[8];
#pragma unroll
        for (int r = 0; r < 8; r++) ar[r] = make_float4(0.f, 0.f, 0.f, 0.f);

        int oh = (beg + half < end) ? __ldg(&vcol[beg + half]) : 0;

        for (int j = beg; j < end; j += 2) {
            int th = j + half;
            bool valid = th < end;
            int ohn = (th + 2 < end) ? __ldg(&vcol[th + 2]) : 0;   // prefetch

            float4 wA = make_float4(0.f, 0.f, 0.f, 0.f), wB = wA;
            if (valid) {
                wA = *(const float4*)&g_l2[(size_t)th * 8];
                wB = *(const float4*)&g_l2[(size_t)th * 8 + 4];
            }
            float4 hv = *(const float4*)&g_h[(size_t)oh * 64 + hl * 4];

            float w0 = wA.x * rv[0], w1 = wA.y * rv[1], w2 = wA.z * rv[2], w3 = wA.w * rv[3];
            float w4 = wB.x * rv[4], w5 = wB.y * rv[5], w6 = wB.z * rv[6], w7 = wB.w * rv[7];

            ar[0].x += w0 * hv.x; ar[0].y += w0 * hv.y; ar[0].z += w0 * hv.z; ar[0].w += w0 * hv.w;
            ar[1].x += w1 * hv.x; ar[1].y += w1 * hv.y; ar[1].z += w1 * hv.z; ar[1].w += w1 * hv.w;
            ar[2].x += w2 * hv.x; ar[2].y += w2 * hv.y; ar[2].z += w2 * hv.z; ar[2].w += w2 * hv.w;
            ar[3].x += w3 * hv.x; ar[3].y += w3 * hv.y; ar[3].z += w3 * hv.z; ar[3].w += w3 * hv.w;
            ar[4].x += w4 * hv.x; ar[4].y += w4 * hv.y; ar[4].z += w4 * hv.z; ar[4].w += w4 * hv.w;
            ar[5].x += w5 * hv.x; ar[5].y += w5 * hv.y; ar[5].z += w5 * hv.z; ar[5].w += w5 * hv.w;
            ar[6].x += w6 * hv.x; ar[6].y += w6 * hv.y; ar[6].z += w6 * hv.z; ar[6].w += w6 * hv.w;
            ar[7].x += w7 * hv.x; ar[7].y += w7 * hv.y; ar[7].z += w7 * hv.z; ar[7].w += w7 * hv.w;

            oh = ohn;
        }
        // combine halves
#pragma unroll
        for (int r = 0; r < 8; r++) {
            ar[r].x += __shfl_xor_sync(FULLM, ar[r].x, 16);
            ar[r].y += __shfl_xor_sync(FULLM, ar[r].y, 16);
            ar[r].z += __shfl_xor_sync(FULLM, ar[r].z, 16);
            ar[r].w += __shfl_xor_sync(FULLM, ar[r].w, 16);
        }
        wa0.x += ar[0].x; wa0.y += ar[0].y; wa0.z += ar[0].z; wa0.w += ar[0].w;

        __syncwarp();
        if (lane < 16) {
#pragma unroll
            for (int r = 1; r < 8; r++)
                *(float4*)&myA[(r - 1) * 64 + lane * 4] = ar[r];
        }
        __syncwarp();

        // contraction: 112 (r,c) pairs, r = 1..7; c = lane & 15
        int c = lane & 15;
#pragma unroll
        for (int i = 0; i < 4; i++) {
            int p = lane + 32 * i;
            if (p < 112) {
                int r = 1 + (p >> 4);
                int v = s * r;
                int q = v / N_NODES;
                int nv = v - q * N_NODES;
                const float4* arow4 = (const float4*)&myA[(r - 1) * 64];
                const float4* w4 = &sW2v[(q * 16) * 16 + c];
                float dot = 0.f;
#pragma unroll
                for (int k = 0; k < 16; k++) {
                    float4 a = arow4[k];
                    float4 w = w4[k * 16];
                    dot += a.x * w.x + a.y * w.y + a.z * w.z + a.w * w.w;
                }
                atomicAdd(&out[(size_t)nv * NCLS + c], dot);
            }
        }
        __syncwarp();
    }

    // flush this warp's r=0 accumulation
    __syncwarp();
    if (lane < 16) *(float4*)&myA[lane * 4] = wa0;
    __syncwarp();
    if (lane < 16) {
        int c = lane;
        const float4* arow4 = (const float4*)myA;
        const float4* w4 = &sW2v[c];
        float dot = 0.f;
#pragma unroll
        for (int k = 0; k < 16; k++) {
            float4 a = arow4[k];
            float4 w = w4[k * 16];
            dot += a.x * w.x + a.y * w.y + a.z * w.z + a.w * w.w;
        }
        atomicAdd(&blockAcc[c], dot);
    }
    __syncthreads();
    if (tid < NCLS) atomicAdd(&out[tid], blockAcc[tid]);
}

// ---------------- launch ----------------
extern "C" void kernel_launch(void* const* d_in, const int* in_sizes, int n_in,
                              void* d_out, int out_size) {
    const float* rm    = (const float*)d_in[0];   // relation_matrix (NT, 64)
    const int*   hrow  = (const int*)d_in[1];     // s tiled (sorted ascending for t<NT)
    const int*   vcol  = (const int*)d_in[4];     // o tiled
    const float* Wl1   = (const float*)d_in[5];
    const float* bl1   = (const float*)d_in[6];
    const float* Wl2   = (const float*)d_in[7];
    const float* bl2   = (const float*)d_in[8];
    const float* w1    = (const float*)d_in[9];   // weights1 (8, 20000, 64)
    const float* w2    = (const float*)d_in[10];  // weights2 (8, 64, 16)
    const float* bias1 = (const float*)d_in[11];
    const float* bias2 = (const float*)d_in[12];
    float* out = (float*)d_out;

    k_init<<<1024, 256>>>(out, bias2, hrow);
    k_phaseA<<<(NT + TPB_A - 1) / TPB_A, 256>>>(rm, hrow, vcol, Wl1, bl1, Wl2, bl2);
    k_recip<<<(NRP + 255) / 256, 256>>>();
    k_h<<<2500, 256>>>(vcol, w1, bias1);
    k_h2logits<<<444, TPB_F>>>(vcol, w2, out);
}